// round 10
// baseline (speedup 1.0000x reference)
#include <cuda_runtime.h>
#include <math.h>

#define NB 32
#define NC 20
#define NN 784
#define NM 392
#define ND 1024
#define NK 4
#define NJ 3
#define NCOLS (NB*NC*4)   // 2560 max packed columns
#define CAP 64            // max class points handled by Gram path
#define CH 64             // Gram chunk columns
#define NCH (ND/CH)       // 16 chunks
#define XSTR (CAP+4)      // sXk row stride

// ---------------- scratch (device globals) ----------------------------------
__device__ int   g_assign[NB*NM];
__device__ float g_sm[NB*NM];
__device__ float g_totsum[NB*ND];
__device__ float g_q0h[NN*ND];
__device__ float g_ph[(size_t)NB*NC*4*ND];
__device__ int   g_cand[NB*NC];
__device__ int   g_big[NB*NC];
__device__ int   g_vlist[NB*NC];
__device__ int   g_vpos[NB*NC];
__device__ int   g_nvalid;
__device__ float g_Km[(size_t)NN*NCOLS];   // [n][packed col], 8 MB
__device__ float g_bce[NB*NC];
__device__ int   g_valid[NB*NC];

// ---------------- helpers ----------------------------------------------------
__device__ __forceinline__ void unpack2(unsigned long long p, float& x, float& y) {
    asm("mov.b64 {%0,%1}, %2;" : "=f"(x), "=f"(y) : "l"(p));
}
__device__ __forceinline__ void ffma2(unsigned long long& c, unsigned long long a,
                                      unsigned long long b) {
    asm("fma.rn.f32x2 %0, %1, %2, %0;" : "+l"(c) : "l"(a), "l"(b));
}

template <int N>
__device__ __forceinline__ void bsumN(float* v, float (*red)[9]) {
    int tid = threadIdx.x, lane = tid & 31, warp = tid >> 5;
    __syncthreads();
    #pragma unroll
    for (int k = 0; k < N; k++) {
        float x = v[k];
        #pragma unroll
        for (int o = 16; o > 0; o >>= 1) x += __shfl_down_sync(0xffffffffu, x, o);
        if (lane == 0) red[k][warp] = x;
    }
    __syncthreads();
    if (tid < N) {
        float s = 0.f;
        #pragma unroll
        for (int w = 0; w < 8; w++) s += red[tid][w];
        red[tid][8] = s;
    }
    __syncthreads();
    #pragma unroll
    for (int k = 0; k < N; k++) v[k] = red[k][8];
}

// ---------------- K1: fused prep (assign+candidacy | totsum | q0h) -----------
__global__ __launch_bounds__(256) void kPrep(const float* __restrict__ query,
                                             const float* __restrict__ score,
                                             const int* __restrict__ label) {
    int blk = blockIdx.x;
    int tid = threadIdx.x;

    if (blk < NB) {
        int b = blk;
        __shared__ int hist[NC];
        if (tid < NC) hist[tid] = 0;
        if (blk == 0 && tid == 0) g_nvalid = 0;
        __syncthreads();
        for (int t = tid; t < NM; t += 256) {
            const float4* s4 = (const float4*)(score + ((size_t)b * NN + 2 * t) * NC);
            float sv[NC];
            #pragma unroll
            for (int q = 0; q < 5; q++) {
                float4 v = s4[q];
                sv[q*4+0] = v.x; sv[q*4+1] = v.y; sv[q*4+2] = v.z; sv[q*4+3] = v.w;
            }
            float best = sv[0]; int bi = 0; float sum = sv[0];
            #pragma unroll
            for (int c = 1; c < NC; c++) {
                float v = sv[c];
                sum += v;
                if (v > best) { best = v; bi = c; }
            }
            g_assign[b * NM + t] = bi;
            g_sm[b * NM + t]     = sum / (float)NC;
            atomicAdd(&hist[bi], 1);
        }
        __syncthreads();
        if (tid < NC) {
            int cnt = hist[tid];
            int cand = (label[b * NC + tid] > 0) && (cnt >= NK);
            int bc = b * NC + tid;
            g_cand[bc] = cand;
            g_big[bc]  = cand && (cnt > CAP);
            if (!cand) { g_bce[bc] = 0.f; g_valid[bc] = 0; }
        }
    } else if (blk < NB + 4 * NB) {
        int i = blk - NB;
        int b = i >> 2;
        int d = (i & 3) * 256 + tid;
        const float* q = query + (size_t)b * NN * ND + d;
        float s = 0.f;
        #pragma unroll 4
        for (int m = 0; m < NM; m++) s += q[(size_t)(2 * m) * ND];
        g_totsum[b * ND + d] = s;
    } else {
        int n = blk - NB - 4 * NB;
        const float* q = query + (size_t)n * ND;
        __shared__ float red[1][9];
        float s[1] = {0.f};
        for (int d = tid; d < ND; d += 256) { float v = q[d]; s[0] += v * v; }
        bsumN<1>(s, red);
        float scale = 1.0f / fmaxf(sqrtf(s[0]), 1e-12f);
        for (int d = tid; d < ND; d += 256)
            g_q0h[(size_t)n * ND + d] = q[d] * scale;
    }
}

// ---------------- Gram compute: pipelined staging + 4x8 register tiles -------
template <int KS>
__device__ __forceinline__ void gramCompute(
    const float* qb, const int* s_list, int count, int nt4, int nt8,
    float (*sXk)[XSTR], float (*sG)[CAP+1], int tid)
{
    int tiles = nt4 * nt8;
    int tile = tid / KS, ksid = tid % KS;
    bool act = (tile < tiles);
    int ti4 = act ? (tile % nt4) : 0;
    int tj8 = act ? (tile / nt4) : 0;

    float acc[4][8];
    #pragma unroll
    for (int r = 0; r < 4; r++)
        #pragma unroll
        for (int c = 0; c < 8; c++) acc[r][c] = 0.f;

    int nload = count * 16;
    float4 pf[4];

    #pragma unroll
    for (int e = 0; e < 4; e++) {
        int i = tid + e * 256;
        if (i < nload)
            pf[e] = *(const float4*)(qb + (size_t)(2 * s_list[i >> 4]) * ND + (i & 15) * 4);
    }

    for (int ch = 0; ch < NCH; ch++) {
        #pragma unroll
        for (int e = 0; e < 4; e++) {
            int i = tid + e * 256;
            if (i < nload) {
                int p = i >> 4, q = i & 15;
                sXk[q*4+0][p] = pf[e].x; sXk[q*4+1][p] = pf[e].y;
                sXk[q*4+2][p] = pf[e].z; sXk[q*4+3][p] = pf[e].w;
            }
        }
        __syncthreads();
        if (ch + 1 < NCH) {
            #pragma unroll
            for (int e = 0; e < 4; e++) {
                int i = tid + e * 256;
                if (i < nload)
                    pf[e] = *(const float4*)(qb + (size_t)(2 * s_list[i >> 4]) * ND
                                             + (ch + 1) * CH + (i & 15) * 4);
            }
        }
        if (act) {
            #pragma unroll 4
            for (int kk = 0; kk < CH / KS; kk++) {
                int k = ksid + kk * KS;
                float4 a  = *(const float4*)&sXk[k][4 * ti4];
                float4 b0 = *(const float4*)&sXk[k][8 * tj8];
                float4 b1 = *(const float4*)&sXk[k][8 * tj8 + 4];
                float av[4] = { a.x, a.y, a.z, a.w };
                float bv[8] = { b0.x, b0.y, b0.z, b0.w, b1.x, b1.y, b1.z, b1.w };
                #pragma unroll
                for (int r = 0; r < 4; r++)
                    #pragma unroll
                    for (int c = 0; c < 8; c++) acc[r][c] += av[r] * bv[c];
            }
        }
        __syncthreads();
    }
    if (act) {
        #pragma unroll
        for (int r = 0; r < 4; r++)
            #pragma unroll
            for (int c = 0; c < 8; c++)
                atomicAdd(&sG[4 * ti4 + r][8 * tj8 + c], acc[r][c]);
    }
    __syncthreads();
}

// ---------------- K2: Gram-matrix k-means + proto build ----------------------
__global__ __launch_bounds__(256, 3) void kKmeansG(const float* __restrict__ query) {
    int bc = blockIdx.x;
    if (!g_cand[bc]) return;
    int b = bc / NC, c = bc % NC;
    int tid = threadIdx.x, lane = tid & 31, warp = tid >> 5;

    if (tid == 0) {
        int pos = atomicAdd(&g_nvalid, 1);
        g_vpos[bc] = pos;
        g_vlist[pos] = bc;
    }

    __shared__ int   s_list[NM];
    __shared__ float sG[CAP][CAP+1];
    __shared__ float sXk[CH][XSTR];
    __shared__ float sw[NJ][CAP];
    __shared__ int   ncnt[NJ];
    __shared__ float sscore[NJ];
    __shared__ int   s_cnt;
    __shared__ int   s_ord[NJ];
    __shared__ float red[8][9];

    if (warp == 0) {
        int cnt = 0;
        for (int base = 0; base < NM; base += 32) {
            int m = base + lane;
            int a = (m < NM) ? g_assign[b * NM + m] : -1;
            unsigned msk = __ballot_sync(0xffffffffu, a == c);
            if (a == c) s_list[cnt + __popc(msk & ((1u << lane) - 1u))] = m;
            cnt += __popc(msk);
        }
        if (lane == 0) s_cnt = cnt;
    }
    __syncthreads();
    int count = s_cnt;
    if (count > CAP) return;

    for (int i = tid; i < CAP * (CAP + 1); i += 256) (&sG[0][0])[i] = 0.f;
    for (int i = tid; i < NJ * CAP; i += 256) {
        int j = i >> 6, p = i & 63;
        sw[j][p] = (p == j) ? 1.f : 0.f;
    }

    const float* qb = query + (size_t)b * NN * ND;

    {
        int nt4 = (count + 3) >> 2, nt8 = (count + 7) >> 3;
        int tiles = nt4 * nt8;
        if      (tiles <= 8)   gramCompute<32>(qb, s_list, count, nt4, nt8, sXk, sG, tid);
        else if (tiles <= 16)  gramCompute<16>(qb, s_list, count, nt4, nt8, sXk, sG, tid);
        else if (tiles <= 32)  gramCompute<8> (qb, s_list, count, nt4, nt8, sXk, sG, tid);
        else if (tiles <= 64)  gramCompute<4> (qb, s_list, count, nt4, nt8, sXk, sG, tid);
        else if (tiles <= 128) gramCompute<2> (qb, s_list, count, nt4, nt8, sXk, sG, tid);
        else                   gramCompute<1> (qb, s_list, count, nt4, nt8, sXk, sG, tid);
    }

    int p = tid;
    bool pact = (p < count);
    float smvp = pact ? g_sm[b * NM + s_list[p]] : 0.f;
    float c2fin[NJ] = {0.f, 0.f, 0.f};

    for (int t = 0; t <= 10; t++) {
        if (tid < NJ) { ncnt[tid] = 0; sscore[tid] = 0.f; }
        float S0 = 0.f, S1 = 0.f, S2 = 0.f;
        if (pact) {
            for (int p2 = 0; p2 < count; p2++) {
                float g = sG[p][p2];
                S0 += sw[0][p2] * g;
                S1 += sw[1][p2] * g;
                S2 += sw[2][p2] * g;
            }
        }
        float v3[NJ];
        v3[0] = pact ? sw[0][p] * S0 : 0.f;
        v3[1] = pact ? sw[1][p] * S1 : 0.f;
        v3[2] = pact ? sw[2][p] * S2 : 0.f;
        bsumN<NJ>(v3, red);
        int jb = 0;
        if (pact) {
            float e0 = v3[0] - 2.f * S0;
            float e1 = v3[1] - 2.f * S1;
            float e2 = v3[2] - 2.f * S2;
            float be = e0;
            if (e1 < be) { be = e1; jb = 1; }
            if (e2 < be) { be = e2; jb = 2; }
            atomicAdd(&ncnt[jb], 1);
            if (t == 10) atomicAdd(&sscore[jb], smvp);
        }
        __syncthreads();
        if (t < 10) {
            if (pact) {
                int n0 = ncnt[0], n1 = ncnt[1], n2 = ncnt[2];
                if (n0 > 0) sw[0][p] = (jb == 0) ? 1.f / (float)n0 : 0.f;
                if (n1 > 0) sw[1][p] = (jb == 1) ? 1.f / (float)n1 : 0.f;
                if (n2 > 0) sw[2][p] = (jb == 2) ? 1.f / (float)n2 : 0.f;
            }
            __syncthreads();
        } else {
            c2fin[0] = v3[0]; c2fin[1] = v3[1]; c2fin[2] = v3[2];
        }
    }

    if (tid == 0) {
        float avg[NJ];
        for (int j = 0; j < NJ; j++)
            avg[j] = (ncnt[j] > 0) ? sscore[j] / (float)ncnt[j] : -INFINITY;
        bool used[NJ] = {false, false, false};
        for (int s = 0; s < NJ; s++) {
            int bi = -1; float bv = 0.f;
            for (int j = 0; j < NJ; j++) {
                if (used[j]) continue;
                if (bi < 0 || avg[j] > bv) { bi = j; bv = avg[j]; }
            }
            used[bi] = true; s_ord[s] = bi;
        }
    }

    int myd = tid * 4;
    float4 a0 = make_float4(0.f,0.f,0.f,0.f), a1 = a0, a2 = a0, cs = a0;
    __syncthreads();
    for (int pp = 0; pp < count; pp++) {
        float w0 = sw[0][pp], w1 = sw[1][pp], w2 = sw[2][pp];
        float4 v = *(const float4*)(qb + (size_t)(2 * s_list[pp]) * ND + myd);
        cs.x += v.x; cs.y += v.y; cs.z += v.z; cs.w += v.w;
        a0.x += w0*v.x; a0.y += w0*v.y; a0.z += w0*v.z; a0.w += w0*v.w;
        a1.x += w1*v.x; a1.y += w1*v.y; a1.z += w1*v.z; a1.w += w1*v.w;
        a2.x += w2*v.x; a2.y += w2*v.y; a2.z += w2*v.z; a2.w += w2*v.w;
    }
    float invden = 1.0f / (float)((NM - count) > 1 ? (NM - count) : 1);
    float4 tsv = *(const float4*)(g_totsum + b * ND + myd);
    float4 bb = make_float4((tsv.x - cs.x)*invden, (tsv.y - cs.y)*invden,
                            (tsv.z - cs.z)*invden, (tsv.w - cs.w)*invden);
    float nb[1] = { bb.x*bb.x + bb.y*bb.y + bb.z*bb.z + bb.w*bb.w };
    bsumN<1>(nb, red);

    float* out = g_ph + (size_t)bc * 4 * ND;
    #pragma unroll
    for (int jj = 0; jj < NJ; jj++) {
        int sj = s_ord[jj];
        float4 av = (sj == 0) ? a0 : ((sj == 1) ? a1 : a2);
        float scale = 1.0f / fmaxf(sqrtf(c2fin[sj]), 1e-12f);
        *(float4*)(out + (size_t)jj * ND + myd) =
            make_float4(av.x*scale, av.y*scale, av.z*scale, av.w*scale);
    }
    {
        float scale = 1.0f / fmaxf(sqrtf(nb[0]), 1e-12f);
        *(float4*)(out + (size_t)3 * ND + myd) =
            make_float4(bb.x*scale, bb.y*scale, bb.z*scale, bb.w*scale);
    }
}

// ---------------- K2b: fallback for count > CAP (rare; usually exits) --------
__global__ __launch_bounds__(256) void kKmeansBig(const float* __restrict__ query) {
    int bc = blockIdx.x;
    if (!g_big[bc]) return;
    int b = bc / NC, c = bc % NC;
    int tid = threadIdx.x, lane = tid & 31, warp = tid >> 5;

    __shared__ float cen[NJ][ND];
    __shared__ int   s_list[NM];
    __shared__ int   s_asg[NM];
    __shared__ int   s_cnt;
    __shared__ int   skcnt[NJ];
    __shared__ float skscore[NJ];
    __shared__ float red[8][9];
    __shared__ int   s_ord[NJ];

    if (warp == 0) {
        int cnt = 0;
        for (int base = 0; base < NM; base += 32) {
            int m = base + lane;
            int a = (m < NM) ? g_assign[b * NM + m] : -1;
            unsigned msk = __ballot_sync(0xffffffffu, a == c);
            if (a == c) s_list[cnt + __popc(msk & ((1u << lane) - 1u))] = m;
            cnt += __popc(msk);
        }
        if (lane == 0) s_cnt = cnt;
    }
    __syncthreads();
    int count = s_cnt;

    const float* qb = query + (size_t)b * NN * ND;
    for (int j = 0; j < NJ; j++) {
        const float* row = qb + (size_t)(2 * s_list[j]) * ND;
        for (int d = tid; d < ND; d += 256) cen[j][d] = row[d];
    }
    float c2r[NJ];
    {
        float nv[NJ] = {0.f, 0.f, 0.f};
        __syncthreads();
        for (int d = tid; d < ND; d += 256) {
            float v0 = cen[0][d], v1 = cen[1][d], v2 = cen[2][d];
            nv[0] += v0*v0; nv[1] += v1*v1; nv[2] += v2*v2;
        }
        bsumN<NJ>(nv, red);
        c2r[0] = nv[0]; c2r[1] = nv[1]; c2r[2] = nv[2];
    }

    int myd = tid * 4;
    float4 csum = make_float4(0.f,0.f,0.f,0.f);

    for (int iter = 0; iter <= 10; iter++) {
        bool finalp = (iter == 10);
        if (tid < NJ) { skcnt[tid] = 0; skscore[tid] = 0.f; }
        __syncthreads();
        for (int p = warp; p < count; p += 8) {
            const float* row = qb + (size_t)(2 * s_list[p]) * ND;
            float d0 = 0.f, d1 = 0.f, d2 = 0.f;
            #pragma unroll
            for (int k = 0; k < 32; k++) {
                float v = row[lane + 32 * k];
                d0 += v * cen[0][lane + 32 * k];
                d1 += v * cen[1][lane + 32 * k];
                d2 += v * cen[2][lane + 32 * k];
            }
            #pragma unroll
            for (int o = 16; o > 0; o >>= 1) {
                d0 += __shfl_down_sync(0xffffffffu, d0, o);
                d1 += __shfl_down_sync(0xffffffffu, d1, o);
                d2 += __shfl_down_sync(0xffffffffu, d2, o);
            }
            if (lane == 0) {
                float e0 = c2r[0] - 2.f * d0;
                float e1 = c2r[1] - 2.f * d1;
                float e2 = c2r[2] - 2.f * d2;
                int jb = 0; float be = e0;
                if (e1 < be) { be = e1; jb = 1; }
                if (e2 < be) { be = e2; jb = 2; }
                s_asg[p] = jb;
                atomicAdd(&skcnt[jb], 1);
                if (finalp) atomicAdd(&skscore[jb], g_sm[b * NM + s_list[p]]);
            }
        }
        __syncthreads();
        if (finalp) break;

        float4 a0 = make_float4(0.f,0.f,0.f,0.f), a1 = a0, a2 = a0;
        for (int p = 0; p < count; p++) {
            int j = s_asg[p];
            float4 v = *(const float4*)(qb + (size_t)(2 * s_list[p]) * ND + myd);
            if (j == 0)      { a0.x += v.x; a0.y += v.y; a0.z += v.z; a0.w += v.w; }
            else if (j == 1) { a1.x += v.x; a1.y += v.y; a1.z += v.z; a1.w += v.w; }
            else             { a2.x += v.x; a2.y += v.y; a2.z += v.z; a2.w += v.w; }
        }
        if (iter == 9) {
            csum.x = a0.x + a1.x + a2.x; csum.y = a0.y + a1.y + a2.y;
            csum.z = a0.z + a1.z + a2.z; csum.w = a0.w + a1.w + a2.w;
        }
        float nv[NJ];
        float4* accs[NJ] = { &a0, &a1, &a2 };
        #pragma unroll
        for (int j = 0; j < NJ; j++) {
            int cnt = skcnt[j];
            float4 cur = make_float4(cen[j][myd], cen[j][myd+1], cen[j][myd+2], cen[j][myd+3]);
            float4 nw;
            if (cnt > 0) {
                float inv = 1.0f / (float)cnt;
                nw = make_float4(accs[j]->x*inv, accs[j]->y*inv, accs[j]->z*inv, accs[j]->w*inv);
            } else nw = cur;
            cen[j][myd]   = nw.x; cen[j][myd+1] = nw.y;
            cen[j][myd+2] = nw.z; cen[j][myd+3] = nw.w;
            nv[j] = nw.x*nw.x + nw.y*nw.y + nw.z*nw.z + nw.w*nw.w;
        }
        bsumN<NJ>(nv, red);
        c2r[0] = nv[0]; c2r[1] = nv[1]; c2r[2] = nv[2];
    }

    if (tid == 0) {
        float avg[NJ];
        for (int j = 0; j < NJ; j++)
            avg[j] = (skcnt[j] > 0) ? skscore[j] / (float)skcnt[j] : -INFINITY;
        bool used[NJ] = {false, false, false};
        for (int s = 0; s < NJ; s++) {
            int bi = -1; float bv = 0.f;
            for (int j = 0; j < NJ; j++) {
                if (used[j]) continue;
                if (bi < 0 || avg[j] > bv) { bi = j; bv = avg[j]; }
            }
            used[bi] = true; s_ord[s] = bi;
        }
    }

    float invden = 1.0f / (float)((NM - count) > 1 ? (NM - count) : 1);
    float4 tsv = *(const float4*)(g_totsum + b * ND + myd);
    float4 bb = make_float4((tsv.x - csum.x)*invden, (tsv.y - csum.y)*invden,
                            (tsv.z - csum.z)*invden, (tsv.w - csum.w)*invden);
    float nb[1] = { bb.x*bb.x + bb.y*bb.y + bb.z*bb.z + bb.w*bb.w };
    bsumN<1>(nb, red);

    float* out = g_ph + (size_t)bc * 4 * ND;
    #pragma unroll
    for (int jj = 0; jj < NJ; jj++) {
        int sj = s_ord[jj];
        float scale = 1.0f / fmaxf(sqrtf(c2r[sj]), 1e-12f);
        *(float4*)(out + (size_t)jj * ND + myd) =
            make_float4(cen[sj][myd]*scale, cen[sj][myd+1]*scale,
                        cen[sj][myd+2]*scale, cen[sj][myd+3]*scale);
    }
    {
        float scale = 1.0f / fmaxf(sqrtf(nb[0]), 1e-12f);
        *(float4*)(out + (size_t)3 * ND + myd) =
            make_float4(bb.x*scale, bb.y*scale, bb.z*scale, bb.w*scale);
    }
}

// ---------------- K3: fp32 GEMM 64x64 tiles + exp epilogue -------------------
// A packed as f32x2 via direct ulonglong2 LDS; B stored DUPLICATED so a
// ulonglong2 LDS yields broadcast {b,b} pairs. No pack MOVs in inner loop.
#define BM 64
#define BN 64
#define BK 16
#define AST (BM + 4)       // 68 floats; row stride 272B (16B-aligned)
#define BST (2*BN + 4)     // 132 floats; row stride 528B (16B-aligned)
__global__ __launch_bounds__(256, 4) void kGemm() {
    int ncols = 4 * g_nvalid;
    int n0 = blockIdx.x * BN;
    if (n0 >= ncols) return;
    int m0 = blockIdx.y * BM;

    __shared__ float As[2][BK][AST];
    __shared__ float Bs[2][BK][BST];

    int tid = threadIdx.x;
    int tm = tid & 15, tn = tid >> 4;    // 16 x 16; thread tile 4(m) x 4(n)
    int lrow = tid >> 2;                  // 0..63
    int lcol = (tid & 3) * 4;             // k offset

    bool amask = (m0 + lrow < NN);
    const float* aptr = g_q0h + (size_t)(amask ? m0 + lrow : 0) * ND + lcol;
    const float* bptr;
    {
        int cl = n0 + lrow;
        int prow = 0;
        if (cl < ncols) prow = g_vlist[cl >> 2] * 4 + (cl & 3);
        bptr = g_ph + (size_t)prow * ND + lcol;
    }

    // preload tile 0
    {
        float4 av = amask ? *(const float4*)aptr : make_float4(0,0,0,0);
        float4 bv = *(const float4*)bptr;
        As[0][lcol+0][lrow] = av.x; As[0][lcol+1][lrow] = av.y;
        As[0][lcol+2][lrow] = av.z; As[0][lcol+3][lrow] = av.w;
        Bs[0][lcol+0][2*lrow] = bv.x; Bs[0][lcol+0][2*lrow+1] = bv.x;
        Bs[0][lcol+1][2*lrow] = bv.y; Bs[0][lcol+1][2*lrow+1] = bv.y;
        Bs[0][lcol+2][2*lrow] = bv.z; Bs[0][lcol+2][2*lrow+1] = bv.z;
        Bs[0][lcol+3][2*lrow] = bv.w; Bs[0][lcol+3][2*lrow+1] = bv.w;
    }
    __syncthreads();

    unsigned long long acc[2][4];
    #pragma unroll
    for (int i = 0; i < 2; i++)
        #pragma unroll
        for (int j = 0; j < 4; j++) acc[i][j] = 0ull;

    const int T = ND / BK;   // 64
    float4 pav, pbv;
    for (int t = 0; t < T; t++) {
        int cur = t & 1;
        if (t < T - 1) {
            int ko = (t + 1) * BK;
            pav = amask ? *(const float4*)(aptr + ko) : make_float4(0,0,0,0);
            pbv = *(const float4*)(bptr + ko);
        }
        #pragma unroll
        for (int kk = 0; kk < BK; kk++) {
            ulonglong2 pa = *(const ulonglong2*)&As[cur][kk][tm * 4];
            ulonglong2 b0 = *(const ulonglong2*)&Bs[cur][kk][tn * 8];
            ulonglong2 b1 = *(const ulonglong2*)&Bs[cur][kk][tn * 8 + 4];
            ffma2(acc[0][0], pa.x, b0.x); ffma2(acc[1][0], pa.y, b0.x);
            ffma2(acc[0][1], pa.x, b0.y); ffma2(acc[1][1], pa.y, b0.y);
            ffma2(acc[0][2], pa.x, b1.x); ffma2(acc[1][2], pa.y, b1.x);
            ffma2(acc[0][3], pa.x, b1.y); ffma2(acc[1][3], pa.y, b1.y);
        }
        if (t < T - 1) {
            __syncthreads();
            int nxt = 1 - cur;
            As[nxt][lcol+0][lrow] = pav.x; As[nxt][lcol+1][lrow] = pav.y;
            As[nxt][lcol+2][lrow] = pav.z; As[nxt][lcol+3][lrow] = pav.w;
            Bs[nxt][lcol+0][2*lrow] = pbv.x; Bs[nxt][lcol+0][2*lrow+1] = pbv.x;
            Bs[nxt][lcol+1][2*lrow] = pbv.y; Bs[nxt][lcol+1][2*lrow+1] = pbv.y;
            Bs[nxt][lcol+2][2*lrow] = pbv.z; Bs[nxt][lcol+2][2*lrow+1] = pbv.z;
            Bs[nxt][lcol+3][2*lrow] = pbv.w; Bs[nxt][lcol+3][2*lrow+1] = pbv.w;
            __syncthreads();
        }
    }

    int colb = n0 + tn * 4;
    if (colb < ncols) {
        #pragma unroll
        for (int i = 0; i < 2; i++) {
            float r0[4], r1[4];
            #pragma unroll
            for (int j = 0; j < 4; j++) unpack2(acc[i][j], r0[j], r1[j]);
            #pragma unroll
            for (int h = 0; h < 2; h++) {
                int m = m0 + tm * 4 + 2 * i + h;
                if (m >= NN) continue;
                float* src = h ? r1 : r0;
                float4 v = make_float4(__expf((src[0]-1.f)*10.f), __expf((src[1]-1.f)*10.f),
                                       __expf((src[2]-1.f)*10.f), __expf((src[3]-1.f)*10.f));
                *(float4*)(g_Km + (size_t)m * NCOLS + colb) = v;
            }
        }
    }
}

// ---------------- K4: Sinkhorn + BCE (register-resident Km) ------------------
__global__ __launch_bounds__(256) void kSink(const float* __restrict__ weights,
                                             const int* __restrict__ gt) {
    int bc = blockIdx.x;
    if (!g_cand[bc]) return;
    int b = bc / NC, c = bc % NC;
    int tid = threadIdx.x;

    __shared__ float red[8][9];
    __shared__ float scc[4];
    __shared__ int   s_done;
    __shared__ int   s_nan;

    int pk4 = g_vpos[bc] * 4;
    float4 km[4]; float rloc[4]; int rows[4]; int nown = 0;
    #pragma unroll
    for (int k = 0; k < 4; k++) {
        int n = tid + 256 * k;
        if (n < NN) {
            rows[nown] = n;
            km[nown] = *(const float4*)(g_Km + (size_t)n * NCOLS + pk4);
            rloc[nown] = 1.f;
            nown++;
        }
    }
    if (tid == 0) { scc[0] = scc[1] = scc[2] = scc[3] = 1.f; s_nan = 0; }
    __syncthreads();

    const float u  = 1.0f / (float)NN;
    const float vv = 1.0f / (float)NK;
    for (int it = 0; it < 100; it++) {
        float lc0 = scc[0], lc1 = scc[1], lc2 = scc[2], lc3 = scc[3];
        float s5[5] = {0.f, 0.f, 0.f, 0.f, 0.f};
        for (int i = 0; i < nown; i++) {
            float4 k4 = km[i];
            float den = k4.x * lc0 + k4.y * lc1 + k4.z * lc2 + k4.w * lc3;
            float r1 = u / den;
            s5[4] += fabsf(r1 - rloc[i]);
            rloc[i] = r1;
            s5[0] += k4.x * r1; s5[1] += k4.y * r1;
            s5[2] += k4.z * r1; s5[3] += k4.w * r1;
        }
        bsumN<5>(s5, red);
        if (tid == 0) {
            scc[0] = vv / s5[0]; scc[1] = vv / s5[1];
            scc[2] = vv / s5[2]; scc[3] = vv / s5[3];
            s_done = (s5[4] / (float)NN < 0.01f) ? 1 : 0;
        }
        __syncthreads();
        if (s_done) break;
    }

    float w0 = weights[0], w1 = weights[1], w2 = weights[2], w3 = weights[3];
    float lc0 = scc[0], lc1 = scc[1], lc2 = scc[2], lc3 = scc[3];
    const int* gtb = gt + b * NN;
    int nanloc = 0;
    float bces[1] = {0.f};
    for (int i = 0; i < nown; i++) {
        int n = rows[i]; float r = rloc[i];
        float t0 = r * lc0 * km[i].x;
        float t1 = r * lc1 * km[i].y;
        float t2 = r * lc2 * km[i].z;
        float t3 = r * lc3 * km[i].w;
        if (isnan(t0) || isnan(t1) || isnan(t2) || isnan(t3)) nanloc = 1;
        float pred = t0 * w0 + t1 * w1 + t2 * w2 + t3 * w3;
        float p  = fminf(fmaxf(pred, 0.f), 1.f);
        float lp = fmaxf(logf(p), -100.f);
        float lq = fmaxf(logf(1.f - p), -100.f);
        int y = (gtb[n] == c + 1);
        bces[0] += -(y ? lp : lq);
    }
    if (nanloc) atomicOr(&s_nan, 1);
    bsumN<1>(bces, red);
    if (tid == 0) {
        if (s_nan) { g_bce[bc] = 0.f; g_valid[bc] = 0; }
        else       { g_bce[bc] = bces[0] / (float)NN; g_valid[bc] = 1; }
    }
}

// ---------------- K5: final reduction ----------------------------------------
__global__ void kFinal(float* __restrict__ out) {
    __shared__ float red[8][9];
    int tid = threadIdx.x;
    float s[2] = {0.f, 0.f};
    for (int i = tid; i < NB * NC; i += 256) {
        s[0] += g_bce[i];
        s[1] += (float)g_valid[i];
    }
    bsumN<2>(s, red);
    if (tid == 0) out[0] = s[0] / (s[1] + 1e-4f);
}

// ---------------- launch -----------------------------------------------------
extern "C" void kernel_launch(void* const* d_in, const int* in_sizes, int n_in,
                              void* d_out, int out_size) {
    const float* query   = (const float*)d_in[0];
    const float* score   = (const float*)d_in[1];
    const int*   label   = (const int*)d_in[2];
    const int*   gt      = (const int*)d_in[3];
    const float* weights = (const float*)d_in[4];
    float* out = (float*)d_out;

    kPrep<<<NB + 4 * NB + NN, 256>>>(query, score, label);
    kKmeansG<<<NB * NC, 256>>>(query);
    kKmeansBig<<<NB * NC, 256>>>(query);
    kGemm<<<dim3(NCOLS / BN, (NN + BM - 1) / BM), 256>>>();
    kSink<<<NB * NC, 256>>>(weights, gt);
    kFinal<<<1, 256>>>(out);
}

// round 11
// speedup vs baseline: 1.3652x; 1.3652x over previous
#include <cuda_runtime.h>
#include <math.h>

#define NB 32
#define NC 20
#define NN 784
#define NM 392
#define ND 1024
#define NK 4
#define NJ 3
#define NCOLS (NB*NC*4)   // 2560 max packed columns
#define CAP 64            // max class points handled by Gram path
#define CH 64             // Gram chunk columns
#define NCH (ND/CH)       // 16 chunks
#define XSTR (CAP+4)      // sXk row stride
#define SPLITK 4
#define KSEG (ND/SPLITK)  // 256

// ---------------- scratch (device globals) ----------------------------------
__device__ int   g_assign[NB*NM];
__device__ float g_sm[NB*NM];
__device__ float g_totsum[NB*ND];
__device__ float g_q0h[NN*ND];
__device__ float g_ph[(size_t)NB*NC*4*ND];
__device__ int   g_cand[NB*NC];
__device__ int   g_big[NB*NC];
__device__ int   g_vlist[NB*NC];
__device__ int   g_vpos[NB*NC];
__device__ int   g_nvalid;
__device__ float g_part[(size_t)SPLITK*NN*NCOLS];  // 32 MB split-K partials
__device__ float g_Km[(size_t)NN*NCOLS];           // [n][packed col], 8 MB
__device__ float g_bce[NB*NC];
__device__ int   g_valid[NB*NC];

// ---------------- helpers ----------------------------------------------------
__device__ __forceinline__ unsigned long long pack2(float x, float y) {
    unsigned long long r;
    asm("mov.b64 %0, {%1,%2};" : "=l"(r) : "f"(x), "f"(y));
    return r;
}
__device__ __forceinline__ void unpack2(unsigned long long p, float& x, float& y) {
    asm("mov.b64 {%0,%1}, %2;" : "=f"(x), "=f"(y) : "l"(p));
}
__device__ __forceinline__ void ffma2(unsigned long long& c, unsigned long long a,
                                      unsigned long long b) {
    asm("fma.rn.f32x2 %0, %1, %2, %0;" : "+l"(c) : "l"(a), "l"(b));
}

template <int N>
__device__ __forceinline__ void bsumN(float* v, float (*red)[9]) {
    int tid = threadIdx.x, lane = tid & 31, warp = tid >> 5;
    __syncthreads();
    #pragma unroll
    for (int k = 0; k < N; k++) {
        float x = v[k];
        #pragma unroll
        for (int o = 16; o > 0; o >>= 1) x += __shfl_down_sync(0xffffffffu, x, o);
        if (lane == 0) red[k][warp] = x;
    }
    __syncthreads();
    if (tid < N) {
        float s = 0.f;
        #pragma unroll
        for (int w = 0; w < 8; w++) s += red[tid][w];
        red[tid][8] = s;
    }
    __syncthreads();
    #pragma unroll
    for (int k = 0; k < N; k++) v[k] = red[k][8];
}

// ---------------- K1: fused prep (assign+candidacy | totsum | q0h) -----------
__global__ __launch_bounds__(256) void kPrep(const float* __restrict__ query,
                                             const float* __restrict__ score,
                                             const int* __restrict__ label) {
    int blk = blockIdx.x;
    int tid = threadIdx.x;

    if (blk < NB) {
        int b = blk;
        __shared__ int hist[NC];
        if (tid < NC) hist[tid] = 0;
        if (blk == 0 && tid == 0) g_nvalid = 0;
        __syncthreads();
        for (int t = tid; t < NM; t += 256) {
            const float4* s4 = (const float4*)(score + ((size_t)b * NN + 2 * t) * NC);
            float sv[NC];
            #pragma unroll
            for (int q = 0; q < 5; q++) {
                float4 v = s4[q];
                sv[q*4+0] = v.x; sv[q*4+1] = v.y; sv[q*4+2] = v.z; sv[q*4+3] = v.w;
            }
            float best = sv[0]; int bi = 0; float sum = sv[0];
            #pragma unroll
            for (int c = 1; c < NC; c++) {
                float v = sv[c];
                sum += v;
                if (v > best) { best = v; bi = c; }
            }
            g_assign[b * NM + t] = bi;
            g_sm[b * NM + t]     = sum / (float)NC;
            atomicAdd(&hist[bi], 1);
        }
        __syncthreads();
        if (tid < NC) {
            int cnt = hist[tid];
            int cand = (label[b * NC + tid] > 0) && (cnt >= NK);
            int bc = b * NC + tid;
            g_cand[bc] = cand;
            g_big[bc]  = cand && (cnt > CAP);
            if (!cand) { g_bce[bc] = 0.f; g_valid[bc] = 0; }
        }
    } else if (blk < NB + 4 * NB) {
        int i = blk - NB;
        int b = i >> 2;
        int d = (i & 3) * 256 + tid;
        const float* q = query + (size_t)b * NN * ND + d;
        float s = 0.f;
        #pragma unroll 4
        for (int m = 0; m < NM; m++) s += q[(size_t)(2 * m) * ND];
        g_totsum[b * ND + d] = s;
    } else {
        int n = blk - NB - 4 * NB;
        const float* q = query + (size_t)n * ND;
        __shared__ float red[1][9];
        float s[1] = {0.f};
        for (int d = tid; d < ND; d += 256) { float v = q[d]; s[0] += v * v; }
        bsumN<1>(s, red);
        float scale = 1.0f / fmaxf(sqrtf(s[0]), 1e-12f);
        for (int d = tid; d < ND; d += 256)
            g_q0h[(size_t)n * ND + d] = q[d] * scale;
    }
}

// ---------------- Gram compute: pipelined staging + 4x8 register tiles -------
template <int KS>
__device__ __forceinline__ void gramCompute(
    const float* qb, const int* s_list, int count, int nt4, int nt8,
    float (*sXk)[XSTR], float (*sG)[CAP+1], int tid)
{
    int tiles = nt4 * nt8;
    int tile = tid / KS, ksid = tid % KS;
    bool act = (tile < tiles);
    int ti4 = act ? (tile % nt4) : 0;
    int tj8 = act ? (tile / nt4) : 0;

    float acc[4][8];
    #pragma unroll
    for (int r = 0; r < 4; r++)
        #pragma unroll
        for (int c = 0; c < 8; c++) acc[r][c] = 0.f;

    int nload = count * 16;
    float4 pf[4];

    #pragma unroll
    for (int e = 0; e < 4; e++) {
        int i = tid + e * 256;
        if (i < nload)
            pf[e] = *(const float4*)(qb + (size_t)(2 * s_list[i >> 4]) * ND + (i & 15) * 4);
    }

    for (int ch = 0; ch < NCH; ch++) {
        #pragma unroll
        for (int e = 0; e < 4; e++) {
            int i = tid + e * 256;
            if (i < nload) {
                int p = i >> 4, q = i & 15;
                sXk[q*4+0][p] = pf[e].x; sXk[q*4+1][p] = pf[e].y;
                sXk[q*4+2][p] = pf[e].z; sXk[q*4+3][p] = pf[e].w;
            }
        }
        __syncthreads();
        if (ch + 1 < NCH) {
            #pragma unroll
            for (int e = 0; e < 4; e++) {
                int i = tid + e * 256;
                if (i < nload)
                    pf[e] = *(const float4*)(qb + (size_t)(2 * s_list[i >> 4]) * ND
                                             + (ch + 1) * CH + (i & 15) * 4);
            }
        }
        if (act) {
            #pragma unroll 4
            for (int kk = 0; kk < CH / KS; kk++) {
                int k = ksid + kk * KS;
                float4 a  = *(const float4*)&sXk[k][4 * ti4];
                float4 b0 = *(const float4*)&sXk[k][8 * tj8];
                float4 b1 = *(const float4*)&sXk[k][8 * tj8 + 4];
                float av[4] = { a.x, a.y, a.z, a.w };
                float bv[8] = { b0.x, b0.y, b0.z, b0.w, b1.x, b1.y, b1.z, b1.w };
                #pragma unroll
                for (int r = 0; r < 4; r++)
                    #pragma unroll
                    for (int c = 0; c < 8; c++) acc[r][c] += av[r] * bv[c];
            }
        }
        __syncthreads();
    }
    if (act) {
        #pragma unroll
        for (int r = 0; r < 4; r++)
            #pragma unroll
            for (int c = 0; c < 8; c++)
                atomicAdd(&sG[4 * ti4 + r][8 * tj8 + c], acc[r][c]);
    }
    __syncthreads();
}

// ---------------- K2: Gram-matrix k-means + proto build ----------------------
__global__ __launch_bounds__(256, 3) void kKmeansG(const float* __restrict__ query) {
    int bc = blockIdx.x;
    if (!g_cand[bc]) return;
    int b = bc / NC, c = bc % NC;
    int tid = threadIdx.x, lane = tid & 31, warp = tid >> 5;

    if (tid == 0) {
        int pos = atomicAdd(&g_nvalid, 1);
        g_vpos[bc] = pos;
        g_vlist[pos] = bc;
    }

    __shared__ int   s_list[NM];
    __shared__ float sG[CAP][CAP+1];
    __shared__ float sXk[CH][XSTR];
    __shared__ float sw[NJ][CAP];
    __shared__ int   ncnt[NJ];
    __shared__ float sscore[NJ];
    __shared__ int   s_cnt;
    __shared__ int   s_ord[NJ];
    __shared__ float red[8][9];

    if (warp == 0) {
        int cnt = 0;
        for (int base = 0; base < NM; base += 32) {
            int m = base + lane;
            int a = (m < NM) ? g_assign[b * NM + m] : -1;
            unsigned msk = __ballot_sync(0xffffffffu, a == c);
            if (a == c) s_list[cnt + __popc(msk & ((1u << lane) - 1u))] = m;
            cnt += __popc(msk);
        }
        if (lane == 0) s_cnt = cnt;
    }
    __syncthreads();
    int count = s_cnt;
    if (count > CAP) return;

    for (int i = tid; i < CAP * (CAP + 1); i += 256) (&sG[0][0])[i] = 0.f;
    for (int i = tid; i < NJ * CAP; i += 256) {
        int j = i >> 6, p = i & 63;
        sw[j][p] = (p == j) ? 1.f : 0.f;
    }

    const float* qb = query + (size_t)b * NN * ND;

    {
        int nt4 = (count + 3) >> 2, nt8 = (count + 7) >> 3;
        int tiles = nt4 * nt8;
        if      (tiles <= 8)   gramCompute<32>(qb, s_list, count, nt4, nt8, sXk, sG, tid);
        else if (tiles <= 16)  gramCompute<16>(qb, s_list, count, nt4, nt8, sXk, sG, tid);
        else if (tiles <= 32)  gramCompute<8> (qb, s_list, count, nt4, nt8, sXk, sG, tid);
        else if (tiles <= 64)  gramCompute<4> (qb, s_list, count, nt4, nt8, sXk, sG, tid);
        else if (tiles <= 128) gramCompute<2> (qb, s_list, count, nt4, nt8, sXk, sG, tid);
        else                   gramCompute<1> (qb, s_list, count, nt4, nt8, sXk, sG, tid);
    }

    int p = tid;
    bool pact = (p < count);
    float smvp = pact ? g_sm[b * NM + s_list[p]] : 0.f;
    float c2fin[NJ] = {0.f, 0.f, 0.f};

    for (int t = 0; t <= 10; t++) {
        if (tid < NJ) { ncnt[tid] = 0; sscore[tid] = 0.f; }
        float S0 = 0.f, S1 = 0.f, S2 = 0.f;
        if (pact) {
            for (int p2 = 0; p2 < count; p2++) {
                float g = sG[p][p2];
                S0 += sw[0][p2] * g;
                S1 += sw[1][p2] * g;
                S2 += sw[2][p2] * g;
            }
        }
        float v3[NJ];
        v3[0] = pact ? sw[0][p] * S0 : 0.f;
        v3[1] = pact ? sw[1][p] * S1 : 0.f;
        v3[2] = pact ? sw[2][p] * S2 : 0.f;
        bsumN<NJ>(v3, red);
        int jb = 0;
        if (pact) {
            float e0 = v3[0] - 2.f * S0;
            float e1 = v3[1] - 2.f * S1;
            float e2 = v3[2] - 2.f * S2;
            float be = e0;
            if (e1 < be) { be = e1; jb = 1; }
            if (e2 < be) { be = e2; jb = 2; }
            atomicAdd(&ncnt[jb], 1);
            if (t == 10) atomicAdd(&sscore[jb], smvp);
        }
        __syncthreads();
        if (t < 10) {
            if (pact) {
                int n0 = ncnt[0], n1 = ncnt[1], n2 = ncnt[2];
                if (n0 > 0) sw[0][p] = (jb == 0) ? 1.f / (float)n0 : 0.f;
                if (n1 > 0) sw[1][p] = (jb == 1) ? 1.f / (float)n1 : 0.f;
                if (n2 > 0) sw[2][p] = (jb == 2) ? 1.f / (float)n2 : 0.f;
            }
            __syncthreads();
        } else {
            c2fin[0] = v3[0]; c2fin[1] = v3[1]; c2fin[2] = v3[2];
        }
    }

    if (tid == 0) {
        float avg[NJ];
        for (int j = 0; j < NJ; j++)
            avg[j] = (ncnt[j] > 0) ? sscore[j] / (float)ncnt[j] : -INFINITY;
        bool used[NJ] = {false, false, false};
        for (int s = 0; s < NJ; s++) {
            int bi = -1; float bv = 0.f;
            for (int j = 0; j < NJ; j++) {
                if (used[j]) continue;
                if (bi < 0 || avg[j] > bv) { bi = j; bv = avg[j]; }
            }
            used[bi] = true; s_ord[s] = bi;
        }
    }

    int myd = tid * 4;
    float4 a0 = make_float4(0.f,0.f,0.f,0.f), a1 = a0, a2 = a0, cs = a0;
    __syncthreads();
    for (int pp = 0; pp < count; pp++) {
        float w0 = sw[0][pp], w1 = sw[1][pp], w2 = sw[2][pp];
        float4 v = *(const float4*)(qb + (size_t)(2 * s_list[pp]) * ND + myd);
        cs.x += v.x; cs.y += v.y; cs.z += v.z; cs.w += v.w;
        a0.x += w0*v.x; a0.y += w0*v.y; a0.z += w0*v.z; a0.w += w0*v.w;
        a1.x += w1*v.x; a1.y += w1*v.y; a1.z += w1*v.z; a1.w += w1*v.w;
        a2.x += w2*v.x; a2.y += w2*v.y; a2.z += w2*v.z; a2.w += w2*v.w;
    }
    float invden = 1.0f / (float)((NM - count) > 1 ? (NM - count) : 1);
    float4 tsv = *(const float4*)(g_totsum + b * ND + myd);
    float4 bb = make_float4((tsv.x - cs.x)*invden, (tsv.y - cs.y)*invden,
                            (tsv.z - cs.z)*invden, (tsv.w - cs.w)*invden);
    float nb[1] = { bb.x*bb.x + bb.y*bb.y + bb.z*bb.z + bb.w*bb.w };
    bsumN<1>(nb, red);

    float* out = g_ph + (size_t)bc * 4 * ND;
    #pragma unroll
    for (int jj = 0; jj < NJ; jj++) {
        int sj = s_ord[jj];
        float4 av = (sj == 0) ? a0 : ((sj == 1) ? a1 : a2);
        float scale = 1.0f / fmaxf(sqrtf(c2fin[sj]), 1e-12f);
        *(float4*)(out + (size_t)jj * ND + myd) =
            make_float4(av.x*scale, av.y*scale, av.z*scale, av.w*scale);
    }
    {
        float scale = 1.0f / fmaxf(sqrtf(nb[0]), 1e-12f);
        *(float4*)(out + (size_t)3 * ND + myd) =
            make_float4(bb.x*scale, bb.y*scale, bb.z*scale, bb.w*scale);
    }
}

// ---------------- K2b: fallback for count > CAP (rare; usually exits) --------
__global__ __launch_bounds__(256) void kKmeansBig(const float* __restrict__ query) {
    int bc = blockIdx.x;
    if (!g_big[bc]) return;
    int b = bc / NC, c = bc % NC;
    int tid = threadIdx.x, lane = tid & 31, warp = tid >> 5;

    __shared__ float cen[NJ][ND];
    __shared__ int   s_list[NM];
    __shared__ int   s_asg[NM];
    __shared__ int   s_cnt;
    __shared__ int   skcnt[NJ];
    __shared__ float skscore[NJ];
    __shared__ float red[8][9];
    __shared__ int   s_ord[NJ];

    if (warp == 0) {
        int cnt = 0;
        for (int base = 0; base < NM; base += 32) {
            int m = base + lane;
            int a = (m < NM) ? g_assign[b * NM + m] : -1;
            unsigned msk = __ballot_sync(0xffffffffu, a == c);
            if (a == c) s_list[cnt + __popc(msk & ((1u << lane) - 1u))] = m;
            cnt += __popc(msk);
        }
        if (lane == 0) s_cnt = cnt;
    }
    __syncthreads();
    int count = s_cnt;

    const float* qb = query + (size_t)b * NN * ND;
    for (int j = 0; j < NJ; j++) {
        const float* row = qb + (size_t)(2 * s_list[j]) * ND;
        for (int d = tid; d < ND; d += 256) cen[j][d] = row[d];
    }
    float c2r[NJ];
    {
        float nv[NJ] = {0.f, 0.f, 0.f};
        __syncthreads();
        for (int d = tid; d < ND; d += 256) {
            float v0 = cen[0][d], v1 = cen[1][d], v2 = cen[2][d];
            nv[0] += v0*v0; nv[1] += v1*v1; nv[2] += v2*v2;
        }
        bsumN<NJ>(nv, red);
        c2r[0] = nv[0]; c2r[1] = nv[1]; c2r[2] = nv[2];
    }

    int myd = tid * 4;
    float4 csum = make_float4(0.f,0.f,0.f,0.f);

    for (int iter = 0; iter <= 10; iter++) {
        bool finalp = (iter == 10);
        if (tid < NJ) { skcnt[tid] = 0; skscore[tid] = 0.f; }
        __syncthreads();
        for (int p = warp; p < count; p += 8) {
            const float* row = qb + (size_t)(2 * s_list[p]) * ND;
            float d0 = 0.f, d1 = 0.f, d2 = 0.f;
            #pragma unroll
            for (int k = 0; k < 32; k++) {
                float v = row[lane + 32 * k];
                d0 += v * cen[0][lane + 32 * k];
                d1 += v * cen[1][lane + 32 * k];
                d2 += v * cen[2][lane + 32 * k];
            }
            #pragma unroll
            for (int o = 16; o > 0; o >>= 1) {
                d0 += __shfl_down_sync(0xffffffffu, d0, o);
                d1 += __shfl_down_sync(0xffffffffu, d1, o);
                d2 += __shfl_down_sync(0xffffffffu, d2, o);
            }
            if (lane == 0) {
                float e0 = c2r[0] - 2.f * d0;
                float e1 = c2r[1] - 2.f * d1;
                float e2 = c2r[2] - 2.f * d2;
                int jb = 0; float be = e0;
                if (e1 < be) { be = e1; jb = 1; }
                if (e2 < be) { be = e2; jb = 2; }
                s_asg[p] = jb;
                atomicAdd(&skcnt[jb], 1);
                if (finalp) atomicAdd(&skscore[jb], g_sm[b * NM + s_list[p]]);
            }
        }
        __syncthreads();
        if (finalp) break;

        float4 a0 = make_float4(0.f,0.f,0.f,0.f), a1 = a0, a2 = a0;
        for (int p = 0; p < count; p++) {
            int j = s_asg[p];
            float4 v = *(const float4*)(qb + (size_t)(2 * s_list[p]) * ND + myd);
            if (j == 0)      { a0.x += v.x; a0.y += v.y; a0.z += v.z; a0.w += v.w; }
            else if (j == 1) { a1.x += v.x; a1.y += v.y; a1.z += v.z; a1.w += v.w; }
            else             { a2.x += v.x; a2.y += v.y; a2.z += v.z; a2.w += v.w; }
        }
        if (iter == 9) {
            csum.x = a0.x + a1.x + a2.x; csum.y = a0.y + a1.y + a2.y;
            csum.z = a0.z + a1.z + a2.z; csum.w = a0.w + a1.w + a2.w;
        }
        float nv[NJ];
        float4* accs[NJ] = { &a0, &a1, &a2 };
        #pragma unroll
        for (int j = 0; j < NJ; j++) {
            int cnt = skcnt[j];
            float4 cur = make_float4(cen[j][myd], cen[j][myd+1], cen[j][myd+2], cen[j][myd+3]);
            float4 nw;
            if (cnt > 0) {
                float inv = 1.0f / (float)cnt;
                nw = make_float4(accs[j]->x*inv, accs[j]->y*inv, accs[j]->z*inv, accs[j]->w*inv);
            } else nw = cur;
            cen[j][myd]   = nw.x; cen[j][myd+1] = nw.y;
            cen[j][myd+2] = nw.z; cen[j][myd+3] = nw.w;
            nv[j] = nw.x*nw.x + nw.y*nw.y + nw.z*nw.z + nw.w*nw.w;
        }
        bsumN<NJ>(nv, red);
        c2r[0] = nv[0]; c2r[1] = nv[1]; c2r[2] = nv[2];
    }

    if (tid == 0) {
        float avg[NJ];
        for (int j = 0; j < NJ; j++)
            avg[j] = (skcnt[j] > 0) ? skscore[j] / (float)skcnt[j] : -INFINITY;
        bool used[NJ] = {false, false, false};
        for (int s = 0; s < NJ; s++) {
            int bi = -1; float bv = 0.f;
            for (int j = 0; j < NJ; j++) {
                if (used[j]) continue;
                if (bi < 0 || avg[j] > bv) { bi = j; bv = avg[j]; }
            }
            used[bi] = true; s_ord[s] = bi;
        }
    }

    float invden = 1.0f / (float)((NM - count) > 1 ? (NM - count) : 1);
    float4 tsv = *(const float4*)(g_totsum + b * ND + myd);
    float4 bb = make_float4((tsv.x - csum.x)*invden, (tsv.y - csum.y)*invden,
                            (tsv.z - csum.z)*invden, (tsv.w - csum.w)*invden);
    float nb[1] = { bb.x*bb.x + bb.y*bb.y + bb.z*bb.z + bb.w*bb.w };
    bsumN<1>(nb, red);

    float* out = g_ph + (size_t)bc * 4 * ND;
    #pragma unroll
    for (int jj = 0; jj < NJ; jj++) {
        int sj = s_ord[jj];
        float scale = 1.0f / fmaxf(sqrtf(c2r[sj]), 1e-12f);
        *(float4*)(out + (size_t)jj * ND + myd) =
            make_float4(cen[sj][myd]*scale, cen[sj][myd+1]*scale,
                        cen[sj][myd+2]*scale, cen[sj][myd+3]*scale);
    }
    {
        float scale = 1.0f / fmaxf(sqrtf(nb[0]), 1e-12f);
        *(float4*)(out + (size_t)3 * ND + myd) =
            make_float4(bb.x*scale, bb.y*scale, bb.z*scale, bb.w*scale);
    }
}

// ---------------- K3: fp32 GEMM 128x64, split-K=4, raw partials --------------
#define BM 128
#define BN 64
#define BK 16
#define BMP (BM + 4)
#define BNP (BN + 4)
__global__ __launch_bounds__(256) void kGemm() {
    int ncols = 4 * g_nvalid;
    int n0 = blockIdx.x * BN;
    if (n0 >= ncols) return;
    int m0 = blockIdx.y * BM;
    int kz = blockIdx.z;
    int kbase = kz * KSEG;

    __shared__ float As[2][BK][BMP];
    __shared__ float Bs[2][BK][BNP];

    int tid = threadIdx.x;
    int tx = tid & 15, ty = tid >> 4;
    int lrow = tid >> 2;
    int lcol = (tid & 3) * 4;

    const float* aptr[2]; bool amask[2];
    #pragma unroll
    for (int r = 0; r < 2; r++) {
        int m = m0 + lrow + 64 * r;
        amask[r] = (m < NN);
        aptr[r] = g_q0h + (size_t)(amask[r] ? m : 0) * ND + kbase + lcol;
    }
    const float* bptr;
    {
        int cl = n0 + lrow;
        int prow = 0;
        if (cl < ncols) prow = g_vlist[cl >> 2] * 4 + (cl & 3);
        bptr = g_ph + (size_t)prow * ND + kbase + lcol;
    }

    #pragma unroll
    for (int r = 0; r < 2; r++) {
        float4 av = amask[r] ? *(const float4*)(aptr[r]) : make_float4(0,0,0,0);
        As[0][lcol+0][lrow+64*r] = av.x; As[0][lcol+1][lrow+64*r] = av.y;
        As[0][lcol+2][lrow+64*r] = av.z; As[0][lcol+3][lrow+64*r] = av.w;
    }
    {
        float4 bv = *(const float4*)(bptr);
        Bs[0][lcol+0][lrow] = bv.x; Bs[0][lcol+1][lrow] = bv.y;
        Bs[0][lcol+2][lrow] = bv.z; Bs[0][lcol+3][lrow] = bv.w;
    }
    __syncthreads();

    unsigned long long acc[4][4];
    #pragma unroll
    for (int i = 0; i < 4; i++)
        #pragma unroll
        for (int j = 0; j < 4; j++) acc[i][j] = 0ull;

    const int T = KSEG / BK;   // 16
    float4 pav[2], pbv;
    for (int t = 0; t < T; t++) {
        int cur = t & 1;
        if (t < T - 1) {
            int ko = (t + 1) * BK;
            #pragma unroll
            for (int r = 0; r < 2; r++)
                pav[r] = amask[r] ? *(const float4*)(aptr[r] + ko) : make_float4(0,0,0,0);
            pbv = *(const float4*)(bptr + ko);
        }
        #pragma unroll
        for (int kk = 0; kk < BK; kk++) {
            float4 alo = *(const float4*)&As[cur][kk][ty * 8];
            float4 ahi = *(const float4*)&As[cur][kk][ty * 8 + 4];
            float4 bv  = *(const float4*)&Bs[cur][kk][tx * 4];
            unsigned long long pa[4];
            pa[0] = pack2(alo.x, alo.y); pa[1] = pack2(alo.z, alo.w);
            pa[2] = pack2(ahi.x, ahi.y); pa[3] = pack2(ahi.z, ahi.w);
            float bvv[4] = { bv.x, bv.y, bv.z, bv.w };
            #pragma unroll
            for (int j = 0; j < 4; j++) {
                unsigned long long bb = pack2(bvv[j], bvv[j]);
                #pragma unroll
                for (int i = 0; i < 4; i++) ffma2(acc[i][j], pa[i], bb);
            }
        }
        if (t < T - 1) {
            __syncthreads();
            int nxt = 1 - cur;
            #pragma unroll
            for (int r = 0; r < 2; r++) {
                As[nxt][lcol+0][lrow+64*r] = pav[r].x; As[nxt][lcol+1][lrow+64*r] = pav[r].y;
                As[nxt][lcol+2][lrow+64*r] = pav[r].z; As[nxt][lcol+3][lrow+64*r] = pav[r].w;
            }
            Bs[nxt][lcol+0][lrow] = pbv.x; Bs[nxt][lcol+1][lrow] = pbv.y;
            Bs[nxt][lcol+2][lrow] = pbv.z; Bs[nxt][lcol+3][lrow] = pbv.w;
            __syncthreads();
        }
    }

    int colb = n0 + tx * 4;
    if (colb < ncols) {
        float* pbase = g_part + (size_t)kz * NN * NCOLS;
        #pragma unroll
        for (int i = 0; i < 4; i++) {
            float r0[4], r1[4];
            #pragma unroll
            for (int j = 0; j < 4; j++) unpack2(acc[i][j], r0[j], r1[j]);
            #pragma unroll
            for (int h = 0; h < 2; h++) {
                int m = m0 + ty * 8 + 2 * i + h;
                if (m >= NN) continue;
                float* src = h ? r1 : r0;
                *(float4*)(pbase + (size_t)m * NCOLS + colb) =
                    make_float4(src[0], src[1], src[2], src[3]);
            }
        }
    }
}

// ---------------- K3b: reduce split-K partials + exp -------------------------
__global__ __launch_bounds__(256) void kRedExp() {
    const size_t stride = (size_t)NN * NCOLS / 4;    // float4 stride per split
    size_t idx = (size_t)blockIdx.x * 256 + threadIdx.x;
    if (idx >= stride) return;
    const float4* p = (const float4*)g_part;
    float4 a = p[idx], b = p[idx + stride], c = p[idx + 2*stride], d = p[idx + 3*stride];
    float4 o;
    o.x = __expf((a.x + b.x + c.x + d.x - 1.f) * 10.f);
    o.y = __expf((a.y + b.y + c.y + d.y - 1.f) * 10.f);
    o.z = __expf((a.z + b.z + c.z + d.z - 1.f) * 10.f);
    o.w = __expf((a.w + b.w + c.w + d.w - 1.f) * 10.f);
    ((float4*)g_Km)[idx] = o;
}

// ---------------- K4: Sinkhorn + BCE (register-resident Km) ------------------
__global__ __launch_bounds__(256) void kSink(const float* __restrict__ weights,
                                             const int* __restrict__ gt) {
    int bc = blockIdx.x;
    if (!g_cand[bc]) return;
    int b = bc / NC, c = bc % NC;
    int tid = threadIdx.x;

    __shared__ float red[8][9];
    __shared__ float scc[4];
    __shared__ int   s_done;
    __shared__ int   s_nan;

    int pk4 = g_vpos[bc] * 4;
    float4 km[4]; float rloc[4]; int rows[4]; int nown = 0;
    #pragma unroll
    for (int k = 0; k < 4; k++) {
        int n = tid + 256 * k;
        if (n < NN) {
            rows[nown] = n;
            km[nown] = *(const float4*)(g_Km + (size_t)n * NCOLS + pk4);
            rloc[nown] = 1.f;
            nown++;
        }
    }
    if (tid == 0) { scc[0] = scc[1] = scc[2] = scc[3] = 1.f; s_nan = 0; }
    __syncthreads();

    const float u  = 1.0f / (float)NN;
    const float vv = 1.0f / (float)NK;
    for (int it = 0; it < 100; it++) {
        float lc0 = scc[0], lc1 = scc[1], lc2 = scc[2], lc3 = scc[3];
        float s5[5] = {0.f, 0.f, 0.f, 0.f, 0.f};
        for (int i = 0; i < nown; i++) {
            float4 k4 = km[i];
            float den = k4.x * lc0 + k4.y * lc1 + k4.z * lc2 + k4.w * lc3;
            float r1 = u / den;
            s5[4] += fabsf(r1 - rloc[i]);
            rloc[i] = r1;
            s5[0] += k4.x * r1; s5[1] += k4.y * r1;
            s5[2] += k4.z * r1; s5[3] += k4.w * r1;
        }
        bsumN<5>(s5, red);
        if (tid == 0) {
            scc[0] = vv / s5[0]; scc[1] = vv / s5[1];
            scc[2] = vv / s5[2]; scc[3] = vv / s5[3];
            s_done = (s5[4] / (float)NN < 0.01f) ? 1 : 0;
        }
        __syncthreads();
        if (s_done) break;
    }

    float w0 = weights[0], w1 = weights[1], w2 = weights[2], w3 = weights[3];
    float lc0 = scc[0], lc1 = scc[1], lc2 = scc[2], lc3 = scc[3];
    const int* gtb = gt + b * NN;
    int nanloc = 0;
    float bces[1] = {0.f};
    for (int i = 0; i < nown; i++) {
        int n = rows[i]; float r = rloc[i];
        float t0 = r * lc0 * km[i].x;
        float t1 = r * lc1 * km[i].y;
        float t2 = r * lc2 * km[i].z;
        float t3 = r * lc3 * km[i].w;
        if (isnan(t0) || isnan(t1) || isnan(t2) || isnan(t3)) nanloc = 1;
        float pred = t0 * w0 + t1 * w1 + t2 * w2 + t3 * w3;
        float p  = fminf(fmaxf(pred, 0.f), 1.f);
        float lp = fmaxf(logf(p), -100.f);
        float lq = fmaxf(logf(1.f - p), -100.f);
        int y = (gtb[n] == c + 1);
        bces[0] += -(y ? lp : lq);
    }
    if (nanloc) atomicOr(&s_nan, 1);
    bsumN<1>(bces, red);
    if (tid == 0) {
        if (s_nan) { g_bce[bc] = 0.f; g_valid[bc] = 0; }
        else       { g_bce[bc] = bces[0] / (float)NN; g_valid[bc] = 1; }
    }
}

// ---------------- K5: final reduction ----------------------------------------
__global__ void kFinal(float* __restrict__ out) {
    __shared__ float red[8][9];
    int tid = threadIdx.x;
    float s[2] = {0.f, 0.f};
    for (int i = tid; i < NB * NC; i += 256) {
        s[0] += g_bce[i];
        s[1] += (float)g_valid[i];
    }
    bsumN<2>(s, red);
    if (tid == 0) out[0] = s[0] / (s[1] + 1e-4f);
}

// ---------------- launch -----------------------------------------------------
extern "C" void kernel_launch(void* const* d_in, const int* in_sizes, int n_in,
                              void* d_out, int out_size) {
    const float* query   = (const float*)d_in[0];
    const float* score   = (const float*)d_in[1];
    const int*   label   = (const int*)d_in[2];
    const int*   gt      = (const int*)d_in[3];
    const float* weights = (const float*)d_in[4];
    float* out = (float*)d_out;

    kPrep<<<NB + 4 * NB + NN, 256>>>(query, score, label);
    kKmeansG<<<NB * NC, 256>>>(query);
    kKmeansBig<<<NB * NC, 256>>>(query);
    kGemm<<<dim3(NCOLS / BN, (NN + BM - 1) / BM, SPLITK), 256>>>();
    kRedExp<<<(NN * NCOLS / 4 + 255) / 256, 256>>>();
    kSink<<<NB * NC, 256>>>(weights, gt);
    kFinal<<<1, 256>>>(out);
}

// round 12
// speedup vs baseline: 1.4875x; 1.0896x over previous
#include <cuda_runtime.h>
#include <math.h>

#define NB 32
#define NC 20
#define NN 784
#define NM 392
#define ND 1024
#define NK 4
#define NJ 3
#define NCOLS (NB*NC*4)   // 2560 max packed columns
#define CAP 64            // max class points handled by Gram path
#define CH 64             // Gram chunk columns
#define NCH (ND/CH)       // 16 chunks
#define XSTR (CAP+4)      // sXk row stride
#define SPLITK 4
#define KSEG (ND/SPLITK)  // 256

// ---------------- scratch (device globals) ----------------------------------
__device__ int   g_assign[NB*NM];
__device__ float g_sm[NB*NM];
__device__ float g_totsum[NB*ND];
__device__ float g_q0h[NN*ND];
__device__ float g_ph[(size_t)NB*NC*4*ND];
__device__ int   g_cand[NB*NC];
__device__ int   g_big[NB*NC];
__device__ int   g_vlist[NB*NC];
__device__ int   g_vpos[NB*NC];
__device__ int   g_nvalid;
__device__ float g_part[(size_t)SPLITK*NN*NCOLS];  // 32 MB split-K partials
__device__ float g_bce[NB*NC];
__device__ int   g_valid[NB*NC];

// ---------------- helpers ----------------------------------------------------
__device__ __forceinline__ unsigned long long pack2(float x, float y) {
    unsigned long long r;
    asm("mov.b64 %0, {%1,%2};" : "=l"(r) : "f"(x), "f"(y));
    return r;
}
__device__ __forceinline__ void unpack2(unsigned long long p, float& x, float& y) {
    asm("mov.b64 {%0,%1}, %2;" : "=f"(x), "=f"(y) : "l"(p));
}
__device__ __forceinline__ void ffma2(unsigned long long& c, unsigned long long a,
                                      unsigned long long b) {
    asm("fma.rn.f32x2 %0, %1, %2, %0;" : "+l"(c) : "l"(a), "l"(b));
}

template <int N>
__device__ __forceinline__ void bsumN(float* v, float (*red)[9]) {
    int tid = threadIdx.x, lane = tid & 31, warp = tid >> 5;
    __syncthreads();
    #pragma unroll
    for (int k = 0; k < N; k++) {
        float x = v[k];
        #pragma unroll
        for (int o = 16; o > 0; o >>= 1) x += __shfl_down_sync(0xffffffffu, x, o);
        if (lane == 0) red[k][warp] = x;
    }
    __syncthreads();
    if (tid < N) {
        float s = 0.f;
        #pragma unroll
        for (int w = 0; w < 8; w++) s += red[tid][w];
        red[tid][8] = s;
    }
    __syncthreads();
    #pragma unroll
    for (int k = 0; k < N; k++) v[k] = red[k][8];
}

// ---------------- K1: fused prep (assign+candidacy | totsum | q0h) -----------
__global__ __launch_bounds__(256) void kPrep(const float* __restrict__ query,
                                             const float* __restrict__ score,
                                             const int* __restrict__ label) {
    int blk = blockIdx.x;
    int tid = threadIdx.x;

    if (blk < NB) {
        int b = blk;
        __shared__ int hist[NC];
        if (tid < NC) hist[tid] = 0;
        if (blk == 0 && tid == 0) g_nvalid = 0;
        __syncthreads();
        for (int t = tid; t < NM; t += 256) {
            const float4* s4 = (const float4*)(score + ((size_t)b * NN + 2 * t) * NC);
            float sv[NC];
            #pragma unroll
            for (int q = 0; q < 5; q++) {
                float4 v = s4[q];
                sv[q*4+0] = v.x; sv[q*4+1] = v.y; sv[q*4+2] = v.z; sv[q*4+3] = v.w;
            }
            float best = sv[0]; int bi = 0; float sum = sv[0];
            #pragma unroll
            for (int c = 1; c < NC; c++) {
                float v = sv[c];
                sum += v;
                if (v > best) { best = v; bi = c; }
            }
            g_assign[b * NM + t] = bi;
            g_sm[b * NM + t]     = sum / (float)NC;
            atomicAdd(&hist[bi], 1);
        }
        __syncthreads();
        if (tid < NC) {
            int cnt = hist[tid];
            int cand = (label[b * NC + tid] > 0) && (cnt >= NK);
            int bc = b * NC + tid;
            g_cand[bc] = cand;
            g_big[bc]  = cand && (cnt > CAP);
            if (!cand) { g_bce[bc] = 0.f; g_valid[bc] = 0; }
        }
    } else if (blk < NB + 4 * NB) {
        int i = blk - NB;
        int b = i >> 2;
        int d = (i & 3) * 256 + tid;
        const float* q = query + (size_t)b * NN * ND + d;
        float s = 0.f;
        #pragma unroll 4
        for (int m = 0; m < NM; m++) s += q[(size_t)(2 * m) * ND];
        g_totsum[b * ND + d] = s;
    } else {
        int n = blk - NB - 4 * NB;
        const float* q = query + (size_t)n * ND;
        __shared__ float red[1][9];
        float s[1] = {0.f};
        for (int d = tid; d < ND; d += 256) { float v = q[d]; s[0] += v * v; }
        bsumN<1>(s, red);
        float scale = 1.0f / fmaxf(sqrtf(s[0]), 1e-12f);
        for (int d = tid; d < ND; d += 256)
            g_q0h[(size_t)n * ND + d] = q[d] * scale;
    }
}

// ---------------- Gram compute: pipelined staging + 4x8 register tiles -------
template <int KS>
__device__ __forceinline__ void gramCompute(
    const float* qb, const int* s_list, int count, int nt4, int nt8,
    float (*sXk)[XSTR], float (*sG)[CAP+1], int tid)
{
    int tiles = nt4 * nt8;
    int tile = tid / KS, ksid = tid % KS;
    bool act = (tile < tiles);
    int ti4 = act ? (tile % nt4) : 0;
    int tj8 = act ? (tile / nt4) : 0;

    float acc[4][8];
    #pragma unroll
    for (int r = 0; r < 4; r++)
        #pragma unroll
        for (int c = 0; c < 8; c++) acc[r][c] = 0.f;

    int nload = count * 16;
    float4 pf[4];

    #pragma unroll
    for (int e = 0; e < 4; e++) {
        int i = tid + e * 256;
        if (i < nload)
            pf[e] = *(const float4*)(qb + (size_t)(2 * s_list[i >> 4]) * ND + (i & 15) * 4);
    }

    for (int ch = 0; ch < NCH; ch++) {
        #pragma unroll
        for (int e = 0; e < 4; e++) {
            int i = tid + e * 256;
            if (i < nload) {
                int p = i >> 4, q = i & 15;
                sXk[q*4+0][p] = pf[e].x; sXk[q*4+1][p] = pf[e].y;
                sXk[q*4+2][p] = pf[e].z; sXk[q*4+3][p] = pf[e].w;
            }
        }
        __syncthreads();
        if (ch + 1 < NCH) {
            #pragma unroll
            for (int e = 0; e < 4; e++) {
                int i = tid + e * 256;
                if (i < nload)
                    pf[e] = *(const float4*)(qb + (size_t)(2 * s_list[i >> 4]) * ND
                                             + (ch + 1) * CH + (i & 15) * 4);
            }
        }
        if (act) {
            #pragma unroll 4
            for (int kk = 0; kk < CH / KS; kk++) {
                int k = ksid + kk * KS;
                float4 a  = *(const float4*)&sXk[k][4 * ti4];
                float4 b0 = *(const float4*)&sXk[k][8 * tj8];
                float4 b1 = *(const float4*)&sXk[k][8 * tj8 + 4];
                float av[4] = { a.x, a.y, a.z, a.w };
                float bv[8] = { b0.x, b0.y, b0.z, b0.w, b1.x, b1.y, b1.z, b1.w };
                #pragma unroll
                for (int r = 0; r < 4; r++)
                    #pragma unroll
                    for (int c = 0; c < 8; c++) acc[r][c] += av[r] * bv[c];
            }
        }
        __syncthreads();
    }
    if (act) {
        #pragma unroll
        for (int r = 0; r < 4; r++)
            #pragma unroll
            for (int c = 0; c < 8; c++)
                atomicAdd(&sG[4 * ti4 + r][8 * tj8 + c], acc[r][c]);
    }
    __syncthreads();
}

// ---------------- K2: Gram-matrix k-means + proto build ----------------------
__global__ __launch_bounds__(256, 3) void kKmeansG(const float* __restrict__ query) {
    int bc = blockIdx.x;
    if (!g_cand[bc]) return;
    int b = bc / NC, c = bc % NC;
    int tid = threadIdx.x, lane = tid & 31, warp = tid >> 5;

    if (tid == 0) {
        int pos = atomicAdd(&g_nvalid, 1);
        g_vpos[bc] = pos;
        g_vlist[pos] = bc;
    }

    __shared__ int   s_list[NM];
    __shared__ float sG[CAP][CAP+1];
    __shared__ float sXk[CH][XSTR];
    __shared__ float sw[NJ][CAP];
    __shared__ int   ncnt[NJ];
    __shared__ float sscore[NJ];
    __shared__ int   s_cnt;
    __shared__ int   s_ord[NJ];
    __shared__ float red[8][9];

    if (warp == 0) {
        int cnt = 0;
        for (int base = 0; base < NM; base += 32) {
            int m = base + lane;
            int a = (m < NM) ? g_assign[b * NM + m] : -1;
            unsigned msk = __ballot_sync(0xffffffffu, a == c);
            if (a == c) s_list[cnt + __popc(msk & ((1u << lane) - 1u))] = m;
            cnt += __popc(msk);
        }
        if (lane == 0) s_cnt = cnt;
    }
    __syncthreads();
    int count = s_cnt;
    if (count > CAP) return;

    for (int i = tid; i < CAP * (CAP + 1); i += 256) (&sG[0][0])[i] = 0.f;
    for (int i = tid; i < NJ * CAP; i += 256) {
        int j = i >> 6, p = i & 63;
        sw[j][p] = (p == j) ? 1.f : 0.f;
    }

    const float* qb = query + (size_t)b * NN * ND;

    {
        int nt4 = (count + 3) >> 2, nt8 = (count + 7) >> 3;
        int tiles = nt4 * nt8;
        if      (tiles <= 8)   gramCompute<32>(qb, s_list, count, nt4, nt8, sXk, sG, tid);
        else if (tiles <= 16)  gramCompute<16>(qb, s_list, count, nt4, nt8, sXk, sG, tid);
        else if (tiles <= 32)  gramCompute<8> (qb, s_list, count, nt4, nt8, sXk, sG, tid);
        else if (tiles <= 64)  gramCompute<4> (qb, s_list, count, nt4, nt8, sXk, sG, tid);
        else if (tiles <= 128) gramCompute<2> (qb, s_list, count, nt4, nt8, sXk, sG, tid);
        else                   gramCompute<1> (qb, s_list, count, nt4, nt8, sXk, sG, tid);
    }

    int p = tid;
    bool pact = (p < count);
    float smvp = pact ? g_sm[b * NM + s_list[p]] : 0.f;
    float c2fin[NJ] = {0.f, 0.f, 0.f};

    for (int t = 0; t <= 10; t++) {
        if (tid < NJ) { ncnt[tid] = 0; sscore[tid] = 0.f; }
        float S0 = 0.f, S1 = 0.f, S2 = 0.f;
        if (pact) {
            for (int p2 = 0; p2 < count; p2++) {
                float g = sG[p][p2];
                S0 += sw[0][p2] * g;
                S1 += sw[1][p2] * g;
                S2 += sw[2][p2] * g;
            }
        }
        float v3[NJ];
        v3[0] = pact ? sw[0][p] * S0 : 0.f;
        v3[1] = pact ? sw[1][p] * S1 : 0.f;
        v3[2] = pact ? sw[2][p] * S2 : 0.f;
        bsumN<NJ>(v3, red);
        int jb = 0;
        if (pact) {
            float e0 = v3[0] - 2.f * S0;
            float e1 = v3[1] - 2.f * S1;
            float e2 = v3[2] - 2.f * S2;
            float be = e0;
            if (e1 < be) { be = e1; jb = 1; }
            if (e2 < be) { be = e2; jb = 2; }
            atomicAdd(&ncnt[jb], 1);
            if (t == 10) atomicAdd(&sscore[jb], smvp);
        }
        __syncthreads();
        if (t < 10) {
            if (pact) {
                int n0 = ncnt[0], n1 = ncnt[1], n2 = ncnt[2];
                if (n0 > 0) sw[0][p] = (jb == 0) ? 1.f / (float)n0 : 0.f;
                if (n1 > 0) sw[1][p] = (jb == 1) ? 1.f / (float)n1 : 0.f;
                if (n2 > 0) sw[2][p] = (jb == 2) ? 1.f / (float)n2 : 0.f;
            }
            __syncthreads();
        } else {
            c2fin[0] = v3[0]; c2fin[1] = v3[1]; c2fin[2] = v3[2];
        }
    }

    if (tid == 0) {
        float avg[NJ];
        for (int j = 0; j < NJ; j++)
            avg[j] = (ncnt[j] > 0) ? sscore[j] / (float)ncnt[j] : -INFINITY;
        bool used[NJ] = {false, false, false};
        for (int s = 0; s < NJ; s++) {
            int bi = -1; float bv = 0.f;
            for (int j = 0; j < NJ; j++) {
                if (used[j]) continue;
                if (bi < 0 || avg[j] > bv) { bi = j; bv = avg[j]; }
            }
            used[bi] = true; s_ord[s] = bi;
        }
    }

    int myd = tid * 4;
    float4 a0 = make_float4(0.f,0.f,0.f,0.f), a1 = a0, a2 = a0, cs = a0;
    __syncthreads();
    for (int pp = 0; pp < count; pp++) {
        float w0 = sw[0][pp], w1 = sw[1][pp], w2 = sw[2][pp];
        float4 v = *(const float4*)(qb + (size_t)(2 * s_list[pp]) * ND + myd);
        cs.x += v.x; cs.y += v.y; cs.z += v.z; cs.w += v.w;
        a0.x += w0*v.x; a0.y += w0*v.y; a0.z += w0*v.z; a0.w += w0*v.w;
        a1.x += w1*v.x; a1.y += w1*v.y; a1.z += w1*v.z; a1.w += w1*v.w;
        a2.x += w2*v.x; a2.y += w2*v.y; a2.z += w2*v.z; a2.w += w2*v.w;
    }
    float invden = 1.0f / (float)((NM - count) > 1 ? (NM - count) : 1);
    float4 tsv = *(const float4*)(g_totsum + b * ND + myd);
    float4 bb = make_float4((tsv.x - cs.x)*invden, (tsv.y - cs.y)*invden,
                            (tsv.z - cs.z)*invden, (tsv.w - cs.w)*invden);
    float nb[1] = { bb.x*bb.x + bb.y*bb.y + bb.z*bb.z + bb.w*bb.w };
    bsumN<1>(nb, red);

    float* out = g_ph + (size_t)bc * 4 * ND;
    #pragma unroll
    for (int jj = 0; jj < NJ; jj++) {
        int sj = s_ord[jj];
        float4 av = (sj == 0) ? a0 : ((sj == 1) ? a1 : a2);
        float scale = 1.0f / fmaxf(sqrtf(c2fin[sj]), 1e-12f);
        *(float4*)(out + (size_t)jj * ND + myd) =
            make_float4(av.x*scale, av.y*scale, av.z*scale, av.w*scale);
    }
    {
        float scale = 1.0f / fmaxf(sqrtf(nb[0]), 1e-12f);
        *(float4*)(out + (size_t)3 * ND + myd) =
            make_float4(bb.x*scale, bb.y*scale, bb.z*scale, bb.w*scale);
    }
}

// ---------------- K2b: fallback for count > CAP (rare; usually exits) --------
__global__ __launch_bounds__(256) void kKmeansBig(const float* __restrict__ query) {
    int bc = blockIdx.x;
    if (!g_big[bc]) return;
    int b = bc / NC, c = bc % NC;
    int tid = threadIdx.x, lane = tid & 31, warp = tid >> 5;

    __shared__ float cen[NJ][ND];
    __shared__ int   s_list[NM];
    __shared__ int   s_asg[NM];
    __shared__ int   s_cnt;
    __shared__ int   skcnt[NJ];
    __shared__ float skscore[NJ];
    __shared__ float red[8][9];
    __shared__ int   s_ord[NJ];

    if (warp == 0) {
        int cnt = 0;
        for (int base = 0; base < NM; base += 32) {
            int m = base + lane;
            int a = (m < NM) ? g_assign[b * NM + m] : -1;
            unsigned msk = __ballot_sync(0xffffffffu, a == c);
            if (a == c) s_list[cnt + __popc(msk & ((1u << lane) - 1u))] = m;
            cnt += __popc(msk);
        }
        if (lane == 0) s_cnt = cnt;
    }
    __syncthreads();
    int count = s_cnt;

    const float* qb = query + (size_t)b * NN * ND;
    for (int j = 0; j < NJ; j++) {
        const float* row = qb + (size_t)(2 * s_list[j]) * ND;
        for (int d = tid; d < ND; d += 256) cen[j][d] = row[d];
    }
    float c2r[NJ];
    {
        float nv[NJ] = {0.f, 0.f, 0.f};
        __syncthreads();
        for (int d = tid; d < ND; d += 256) {
            float v0 = cen[0][d], v1 = cen[1][d], v2 = cen[2][d];
            nv[0] += v0*v0; nv[1] += v1*v1; nv[2] += v2*v2;
        }
        bsumN<NJ>(nv, red);
        c2r[0] = nv[0]; c2r[1] = nv[1]; c2r[2] = nv[2];
    }

    int myd = tid * 4;
    float4 csum = make_float4(0.f,0.f,0.f,0.f);

    for (int iter = 0; iter <= 10; iter++) {
        bool finalp = (iter == 10);
        if (tid < NJ) { skcnt[tid] = 0; skscore[tid] = 0.f; }
        __syncthreads();
        for (int p = warp; p < count; p += 8) {
            const float* row = qb + (size_t)(2 * s_list[p]) * ND;
            float d0 = 0.f, d1 = 0.f, d2 = 0.f;
            #pragma unroll
            for (int k = 0; k < 32; k++) {
                float v = row[lane + 32 * k];
                d0 += v * cen[0][lane + 32 * k];
                d1 += v * cen[1][lane + 32 * k];
                d2 += v * cen[2][lane + 32 * k];
            }
            #pragma unroll
            for (int o = 16; o > 0; o >>= 1) {
                d0 += __shfl_down_sync(0xffffffffu, d0, o);
                d1 += __shfl_down_sync(0xffffffffu, d1, o);
                d2 += __shfl_down_sync(0xffffffffu, d2, o);
            }
            if (lane == 0) {
                float e0 = c2r[0] - 2.f * d0;
                float e1 = c2r[1] - 2.f * d1;
                float e2 = c2r[2] - 2.f * d2;
                int jb = 0; float be = e0;
                if (e1 < be) { be = e1; jb = 1; }
                if (e2 < be) { be = e2; jb = 2; }
                s_asg[p] = jb;
                atomicAdd(&skcnt[jb], 1);
                if (finalp) atomicAdd(&skscore[jb], g_sm[b * NM + s_list[p]]);
            }
        }
        __syncthreads();
        if (finalp) break;

        float4 a0 = make_float4(0.f,0.f,0.f,0.f), a1 = a0, a2 = a0;
        for (int p = 0; p < count; p++) {
            int j = s_asg[p];
            float4 v = *(const float4*)(qb + (size_t)(2 * s_list[p]) * ND + myd);
            if (j == 0)      { a0.x += v.x; a0.y += v.y; a0.z += v.z; a0.w += v.w; }
            else if (j == 1) { a1.x += v.x; a1.y += v.y; a1.z += v.z; a1.w += v.w; }
            else             { a2.x += v.x; a2.y += v.y; a2.z += v.z; a2.w += v.w; }
        }
        if (iter == 9) {
            csum.x = a0.x + a1.x + a2.x; csum.y = a0.y + a1.y + a2.y;
            csum.z = a0.z + a1.z + a2.z; csum.w = a0.w + a1.w + a2.w;
        }
        float nv[NJ];
        float4* accs[NJ] = { &a0, &a1, &a2 };
        #pragma unroll
        for (int j = 0; j < NJ; j++) {
            int cnt = skcnt[j];
            float4 cur = make_float4(cen[j][myd], cen[j][myd+1], cen[j][myd+2], cen[j][myd+3]);
            float4 nw;
            if (cnt > 0) {
                float inv = 1.0f / (float)cnt;
                nw = make_float4(accs[j]->x*inv, accs[j]->y*inv, accs[j]->z*inv, accs[j]->w*inv);
            } else nw = cur;
            cen[j][myd]   = nw.x; cen[j][myd+1] = nw.y;
            cen[j][myd+2] = nw.z; cen[j][myd+3] = nw.w;
            nv[j] = nw.x*nw.x + nw.y*nw.y + nw.z*nw.z + nw.w*nw.w;
        }
        bsumN<NJ>(nv, red);
        c2r[0] = nv[0]; c2r[1] = nv[1]; c2r[2] = nv[2];
    }

    if (tid == 0) {
        float avg[NJ];
        for (int j = 0; j < NJ; j++)
            avg[j] = (skcnt[j] > 0) ? skscore[j] / (float)skcnt[j] : -INFINITY;
        bool used[NJ] = {false, false, false};
        for (int s = 0; s < NJ; s++) {
            int bi = -1; float bv = 0.f;
            for (int j = 0; j < NJ; j++) {
                if (used[j]) continue;
                if (bi < 0 || avg[j] > bv) { bi = j; bv = avg[j]; }
            }
            used[bi] = true; s_ord[s] = bi;
        }
    }

    float invden = 1.0f / (float)((NM - count) > 1 ? (NM - count) : 1);
    float4 tsv = *(const float4*)(g_totsum + b * ND + myd);
    float4 bb = make_float4((tsv.x - csum.x)*invden, (tsv.y - csum.y)*invden,
                            (tsv.z - csum.z)*invden, (tsv.w - csum.w)*invden);
    float nb[1] = { bb.x*bb.x + bb.y*bb.y + bb.z*bb.z + bb.w*bb.w };
    bsumN<1>(nb, red);

    float* out = g_ph + (size_t)bc * 4 * ND;
    #pragma unroll
    for (int jj = 0; jj < NJ; jj++) {
        int sj = s_ord[jj];
        float scale = 1.0f / fmaxf(sqrtf(c2r[sj]), 1e-12f);
        *(float4*)(out + (size_t)jj * ND + myd) =
            make_float4(cen[sj][myd]*scale, cen[sj][myd+1]*scale,
                        cen[sj][myd+2]*scale, cen[sj][myd+3]*scale);
    }
    {
        float scale = 1.0f / fmaxf(sqrtf(nb[0]), 1e-12f);
        *(float4*)(out + (size_t)3 * ND + myd) =
            make_float4(bb.x*scale, bb.y*scale, bb.z*scale, bb.w*scale);
    }
}

// ---------------- K3: fp32 GEMM 128x64, split-K=4, raw partials --------------
#define BM 128
#define BN 64
#define BK 16
#define BMP (BM + 4)
#define BNP (BN + 4)
__global__ __launch_bounds__(256) void kGemm() {
    int ncols = 4 * g_nvalid;
    int n0 = blockIdx.x * BN;
    if (n0 >= ncols) return;
    int m0 = blockIdx.y * BM;
    int kz = blockIdx.z;
    int kbase = kz * KSEG;

    __shared__ float As[2][BK][BMP];
    __shared__ float Bs[2][BK][BNP];

    int tid = threadIdx.x;
    int tx = tid & 15, ty = tid >> 4;
    int lrow = tid >> 2;
    int lcol = (tid & 3) * 4;

    const float* aptr[2]; bool amask[2];
    #pragma unroll
    for (int r = 0; r < 2; r++) {
        int m = m0 + lrow + 64 * r;
        amask[r] = (m < NN);
        aptr[r] = g_q0h + (size_t)(amask[r] ? m : 0) * ND + kbase + lcol;
    }
    const float* bptr;
    {
        int cl = n0 + lrow;
        int prow = 0;
        if (cl < ncols) prow = g_vlist[cl >> 2] * 4 + (cl & 3);
        bptr = g_ph + (size_t)prow * ND + kbase + lcol;
    }

    #pragma unroll
    for (int r = 0; r < 2; r++) {
        float4 av = amask[r] ? *(const float4*)(aptr[r]) : make_float4(0,0,0,0);
        As[0][lcol+0][lrow+64*r] = av.x; As[0][lcol+1][lrow+64*r] = av.y;
        As[0][lcol+2][lrow+64*r] = av.z; As[0][lcol+3][lrow+64*r] = av.w;
    }
    {
        float4 bv = *(const float4*)(bptr);
        Bs[0][lcol+0][lrow] = bv.x; Bs[0][lcol+1][lrow] = bv.y;
        Bs[0][lcol+2][lrow] = bv.z; Bs[0][lcol+3][lrow] = bv.w;
    }
    __syncthreads();

    unsigned long long acc[4][4];
    #pragma unroll
    for (int i = 0; i < 4; i++)
        #pragma unroll
        for (int j = 0; j < 4; j++) acc[i][j] = 0ull;

    const int T = KSEG / BK;   // 16
    float4 pav[2], pbv;
    for (int t = 0; t < T; t++) {
        int cur = t & 1;
        if (t < T - 1) {
            int ko = (t + 1) * BK;
            #pragma unroll
            for (int r = 0; r < 2; r++)
                pav[r] = amask[r] ? *(const float4*)(aptr[r] + ko) : make_float4(0,0,0,0);
            pbv = *(const float4*)(bptr + ko);
        }
        #pragma unroll
        for (int kk = 0; kk < BK; kk++) {
            // A pairs loaded directly as f32x2 (adjacent floats) — no pack MOVs
            ulonglong2 palo = *(const ulonglong2*)&As[cur][kk][ty * 8];
            ulonglong2 pahi = *(const ulonglong2*)&As[cur][kk][ty * 8 + 4];
            float4 bv  = *(const float4*)&Bs[cur][kk][tx * 4];
            unsigned long long bb0 = pack2(bv.x, bv.x);
            unsigned long long bb1 = pack2(bv.y, bv.y);
            unsigned long long bb2 = pack2(bv.z, bv.z);
            unsigned long long bb3 = pack2(bv.w, bv.w);
            ffma2(acc[0][0], palo.x, bb0); ffma2(acc[1][0], palo.y, bb0);
            ffma2(acc[2][0], pahi.x, bb0); ffma2(acc[3][0], pahi.y, bb0);
            ffma2(acc[0][1], palo.x, bb1); ffma2(acc[1][1], palo.y, bb1);
            ffma2(acc[2][1], pahi.x, bb1); ffma2(acc[3][1], pahi.y, bb1);
            ffma2(acc[0][2], palo.x, bb2); ffma2(acc[1][2], palo.y, bb2);
            ffma2(acc[2][2], pahi.x, bb2); ffma2(acc[3][2], pahi.y, bb2);
            ffma2(acc[0][3], palo.x, bb3); ffma2(acc[1][3], palo.y, bb3);
            ffma2(acc[2][3], pahi.x, bb3); ffma2(acc[3][3], pahi.y, bb3);
        }
        if (t < T - 1) {
            __syncthreads();
            int nxt = 1 - cur;
            #pragma unroll
            for (int r = 0; r < 2; r++) {
                As[nxt][lcol+0][lrow+64*r] = pav[r].x; As[nxt][lcol+1][lrow+64*r] = pav[r].y;
                As[nxt][lcol+2][lrow+64*r] = pav[r].z; As[nxt][lcol+3][lrow+64*r] = pav[r].w;
            }
            Bs[nxt][lcol+0][lrow] = pbv.x; Bs[nxt][lcol+1][lrow] = pbv.y;
            Bs[nxt][lcol+2][lrow] = pbv.z; Bs[nxt][lcol+3][lrow] = pbv.w;
            __syncthreads();
        }
    }

    int colb = n0 + tx * 4;
    if (colb < ncols) {
        float* pbase = g_part + (size_t)kz * NN * NCOLS;
        #pragma unroll
        for (int i = 0; i < 4; i++) {
            float r0[4], r1[4];
            #pragma unroll
            for (int j = 0; j < 4; j++) unpack2(acc[i][j], r0[j], r1[j]);
            #pragma unroll
            for (int h = 0; h < 2; h++) {
                int m = m0 + ty * 8 + 2 * i + h;
                if (m >= NN) continue;
                float* src = h ? r1 : r0;
                *(float4*)(pbase + (size_t)m * NCOLS + colb) =
                    make_float4(src[0], src[1], src[2], src[3]);
            }
        }
    }
}

// ---------------- K4: Sinkhorn + BCE (fused split-K reduce + exp) ------------
__global__ __launch_bounds__(256) void kSink(const float* __restrict__ weights,
                                             const int* __restrict__ gt) {
    int bc = blockIdx.x;
    if (!g_cand[bc]) return;
    int b = bc / NC, c = bc % NC;
    int tid = threadIdx.x;

    __shared__ float red[8][9];
    __shared__ float scc[4];
    __shared__ int   s_done;
    __shared__ int   s_nan;

    int pk4 = g_vpos[bc] * 4;
    const size_t ss = (size_t)NN * NCOLS;
    float4 km[4]; float rloc[4]; int rows[4]; int nown = 0;
    #pragma unroll
    for (int k = 0; k < 4; k++) {
        int n = tid + 256 * k;
        if (n < NN) {
            const float* pp = g_part + (size_t)n * NCOLS + pk4;
            float4 a = *(const float4*)(pp);
            float4 bq = *(const float4*)(pp + ss);
            float4 cq = *(const float4*)(pp + 2 * ss);
            float4 dq = *(const float4*)(pp + 3 * ss);
            float4 o;
            o.x = __expf((a.x + bq.x + cq.x + dq.x - 1.f) * 10.f);
            o.y = __expf((a.y + bq.y + cq.y + dq.y - 1.f) * 10.f);
            o.z = __expf((a.z + bq.z + cq.z + dq.z - 1.f) * 10.f);
            o.w = __expf((a.w + bq.w + cq.w + dq.w - 1.f) * 10.f);
            rows[nown] = n;
            km[nown] = o;
            rloc[nown] = 1.f;
            nown++;
        }
    }
    if (tid == 0) { scc[0] = scc[1] = scc[2] = scc[3] = 1.f; s_nan = 0; }
    __syncthreads();

    const float u  = 1.0f / (float)NN;
    const float vv = 1.0f / (float)NK;
    for (int it = 0; it < 100; it++) {
        float lc0 = scc[0], lc1 = scc[1], lc2 = scc[2], lc3 = scc[3];
        float s5[5] = {0.f, 0.f, 0.f, 0.f, 0.f};
        for (int i = 0; i < nown; i++) {
            float4 k4 = km[i];
            float den = k4.x * lc0 + k4.y * lc1 + k4.z * lc2 + k4.w * lc3;
            float r1 = u / den;
            s5[4] += fabsf(r1 - rloc[i]);
            rloc[i] = r1;
            s5[0] += k4.x * r1; s5[1] += k4.y * r1;
            s5[2] += k4.z * r1; s5[3] += k4.w * r1;
        }
        bsumN<5>(s5, red);
        if (tid == 0) {
            scc[0] = vv / s5[0]; scc[1] = vv / s5[1];
            scc[2] = vv / s5[2]; scc[3] = vv / s5[3];
            s_done = (s5[4] / (float)NN < 0.01f) ? 1 : 0;
        }
        __syncthreads();
        if (s_done) break;
    }

    float w0 = weights[0], w1 = weights[1], w2 = weights[2], w3 = weights[3];
    float lc0 = scc[0], lc1 = scc[1], lc2 = scc[2], lc3 = scc[3];
    const int* gtb = gt + b * NN;
    int nanloc = 0;
    float bces[1] = {0.f};
    for (int i = 0; i < nown; i++) {
        int n = rows[i]; float r = rloc[i];
        float t0 = r * lc0 * km[i].x;
        float t1 = r * lc1 * km[i].y;
        float t2 = r * lc2 * km[i].z;
        float t3 = r * lc3 * km[i].w;
        if (isnan(t0) || isnan(t1) || isnan(t2) || isnan(t3)) nanloc = 1;
        float pred = t0 * w0 + t1 * w1 + t2 * w2 + t3 * w3;
        float p  = fminf(fmaxf(pred, 0.f), 1.f);
        float lp = fmaxf(logf(p), -100.f);
        float lq = fmaxf(logf(1.f - p), -100.f);
        int y = (gtb[n] == c + 1);
        bces[0] += -(y ? lp : lq);
    }
    if (nanloc) atomicOr(&s_nan, 1);
    bsumN<1>(bces, red);
    if (tid == 0) {
        if (s_nan) { g_bce[bc] = 0.f; g_valid[bc] = 0; }
        else       { g_bce[bc] = bces[0] / (float)NN; g_valid[bc] = 1; }
    }
}

// ---------------- K5: final reduction ----------------------------------------
__global__ void kFinal(float* __restrict__ out) {
    __shared__ float red[8][9];
    int tid = threadIdx.x;
    float s[2] = {0.f, 0.f};
    for (int i = tid; i < NB * NC; i += 256) {
        s[0] += g_bce[i];
        s[1] += (float)g_valid[i];
    }
    bsumN<2>(s, red);
    if (tid == 0) out[0] = s[0] / (s[1] + 1e-4f);
}

// ---------------- launch -----------------------------------------------------
extern "C" void kernel_launch(void* const* d_in, const int* in_sizes, int n_in,
                              void* d_out, int out_size) {
    const float* query   = (const float*)d_in[0];
    const float* score   = (const float*)d_in[1];
    const int*   label   = (const int*)d_in[2];
    const int*   gt      = (const int*)d_in[3];
    const float* weights = (const float*)d_in[4];
    float* out = (float*)d_out;

    kPrep<<<NB + 4 * NB + NN, 256>>>(query, score, label);
    kKmeansG<<<NB * NC, 256>>>(query);
    kKmeansBig<<<NB * NC, 256>>>(query);
    kGemm<<<dim3(NCOLS / BN, (NN + BM - 1) / BM, SPLITK), 256>>>();
    kSink<<<NB * NC, 256>>>(weights, gt);
    kFinal<<<1, 256>>>(out);
}

// round 15
// speedup vs baseline: 1.4923x; 1.0032x over previous
#include <cuda_runtime.h>
#include <math.h>

#define NB 32
#define NC 20
#define NN 784
#define NM 392
#define ND 1024
#define NK 4
#define NJ 3
#define NCOLS (NB*NC*4)   // 2560 max packed columns
#define CAP 64            // max class points handled by Gram path
#define CH 64             // Gram chunk columns
#define NCH (ND/CH)       // 16 chunks
#define XSTR (CAP+4)      // sXk row stride
#define SPLITK 4
#define KSEG (ND/SPLITK)  // 256

// ---------------- scratch (device globals) ----------------------------------
__device__ int   g_assign[NB*NM];
__device__ float g_sm[NB*NM];
__device__ float g_totsum[NB*ND];
__device__ float g_q0h[NN*ND];
__device__ float g_ph[(size_t)NB*NC*4*ND];
__device__ int   g_cand[NB*NC];
__device__ int   g_big[NB*NC];
__device__ int   g_vlist[NB*NC];
__device__ int   g_vpos[NB*NC];
__device__ int   g_nvalid;
__device__ float g_part[(size_t)SPLITK*NN*NCOLS];  // 32 MB split-K partials
__device__ float g_bce[NB*NC];
__device__ int   g_valid[NB*NC];

// ---------------- helpers ----------------------------------------------------
__device__ __forceinline__ unsigned long long pack2(float x, float y) {
    unsigned long long r;
    asm("mov.b64 %0, {%1,%2};" : "=l"(r) : "f"(x), "f"(y));
    return r;
}
__device__ __forceinline__ void unpack2(unsigned long long p, float& x, float& y) {
    asm("mov.b64 {%0,%1}, %2;" : "=f"(x), "=f"(y) : "l"(p));
}
__device__ __forceinline__ void ffma2(unsigned long long& c, unsigned long long a,
                                      unsigned long long b) {
    asm("fma.rn.f32x2 %0, %1, %2, %0;" : "+l"(c) : "l"(a), "l"(b));
}

template <int N>
__device__ __forceinline__ void bsumN(float* v, float (*red)[9]) {
    int tid = threadIdx.x, lane = tid & 31, warp = tid >> 5;
    __syncthreads();
    #pragma unroll
    for (int k = 0; k < N; k++) {
        float x = v[k];
        #pragma unroll
        for (int o = 16; o > 0; o >>= 1) x += __shfl_down_sync(0xffffffffu, x, o);
        if (lane == 0) red[k][warp] = x;
    }
    __syncthreads();
    if (tid < N) {
        float s = 0.f;
        #pragma unroll
        for (int w = 0; w < 8; w++) s += red[tid][w];
        red[tid][8] = s;
    }
    __syncthreads();
    #pragma unroll
    for (int k = 0; k < N; k++) v[k] = red[k][8];
}

// ---------------- K1: fused prep (assign+candidacy | totsum | q0h) -----------
__global__ __launch_bounds__(256) void kPrep(const float* __restrict__ query,
                                             const float* __restrict__ score,
                                             const int* __restrict__ label) {
    int blk = blockIdx.x;
    int tid = threadIdx.x;

    if (blk < NB) {
        int b = blk;
        __shared__ int hist[NC];
        if (tid < NC) hist[tid] = 0;
        if (blk == 0 && tid == 0) g_nvalid = 0;
        __syncthreads();
        for (int t = tid; t < NM; t += 256) {
            const float4* s4 = (const float4*)(score + ((size_t)b * NN + 2 * t) * NC);
            float sv[NC];
            #pragma unroll
            for (int q = 0; q < 5; q++) {
                float4 v = s4[q];
                sv[q*4+0] = v.x; sv[q*4+1] = v.y; sv[q*4+2] = v.z; sv[q*4+3] = v.w;
            }
            float best = sv[0]; int bi = 0; float sum = sv[0];
            #pragma unroll
            for (int c = 1; c < NC; c++) {
                float v = sv[c];
                sum += v;
                if (v > best) { best = v; bi = c; }
            }
            g_assign[b * NM + t] = bi;
            g_sm[b * NM + t]     = sum / (float)NC;
            atomicAdd(&hist[bi], 1);
        }
        __syncthreads();
        if (tid < NC) {
            int cnt = hist[tid];
            int cand = (label[b * NC + tid] > 0) && (cnt >= NK);
            int bc = b * NC + tid;
            g_cand[bc] = cand;
            g_big[bc]  = cand && (cnt > CAP);
            if (!cand) { g_bce[bc] = 0.f; g_valid[bc] = 0; }
        }
    } else if (blk < NB + 4 * NB) {
        int i = blk - NB;
        int b = i >> 2;
        int d = (i & 3) * 256 + tid;
        const float* q = query + (size_t)b * NN * ND + d;
        float s = 0.f;
        #pragma unroll 4
        for (int m = 0; m < NM; m++) s += q[(size_t)(2 * m) * ND];
        g_totsum[b * ND + d] = s;
    } else {
        int n = blk - NB - 4 * NB;
        const float* q = query + (size_t)n * ND;
        __shared__ float red[1][9];
        float s[1] = {0.f};
        for (int d = tid; d < ND; d += 256) { float v = q[d]; s[0] += v * v; }
        bsumN<1>(s, red);
        float scale = 1.0f / fmaxf(sqrtf(s[0]), 1e-12f);
        for (int d = tid; d < ND; d += 256)
            g_q0h[(size_t)n * ND + d] = q[d] * scale;
    }
}

// ---------------- Gram compute: pipelined staging + 4x8 register tiles -------
template <int KS>
__device__ __forceinline__ void gramCompute(
    const float* qb, const int* s_list, int count, int nt4, int nt8,
    float (*sXk)[XSTR], float (*sG)[CAP+1], int tid)
{
    int tiles = nt4 * nt8;
    int tile = tid / KS, ksid = tid % KS;
    bool act = (tile < tiles);
    int ti4 = act ? (tile % nt4) : 0;
    int tj8 = act ? (tile / nt4) : 0;

    float acc[4][8];
    #pragma unroll
    for (int r = 0; r < 4; r++)
        #pragma unroll
        for (int c = 0; c < 8; c++) acc[r][c] = 0.f;

    int nload = count * 16;
    float4 pf[4];

    #pragma unroll
    for (int e = 0; e < 4; e++) {
        int i = tid + e * 256;
        if (i < nload)
            pf[e] = *(const float4*)(qb + (size_t)(2 * s_list[i >> 4]) * ND + (i & 15) * 4);
    }

    for (int ch = 0; ch < NCH; ch++) {
        #pragma unroll
        for (int e = 0; e < 4; e++) {
            int i = tid + e * 256;
            if (i < nload) {
                int p = i >> 4, q = i & 15;
                sXk[q*4+0][p] = pf[e].x; sXk[q*4+1][p] = pf[e].y;
                sXk[q*4+2][p] = pf[e].z; sXk[q*4+3][p] = pf[e].w;
            }
        }
        __syncthreads();
        if (ch + 1 < NCH) {
            #pragma unroll
            for (int e = 0; e < 4; e++) {
                int i = tid + e * 256;
                if (i < nload)
                    pf[e] = *(const float4*)(qb + (size_t)(2 * s_list[i >> 4]) * ND
                                             + (ch + 1) * CH + (i & 15) * 4);
            }
        }
        if (act) {
            #pragma unroll 4
            for (int kk = 0; kk < CH / KS; kk++) {
                int k = ksid + kk * KS;
                float4 a  = *(const float4*)&sXk[k][4 * ti4];
                float4 b0 = *(const float4*)&sXk[k][8 * tj8];
                float4 b1 = *(const float4*)&sXk[k][8 * tj8 + 4];
                float av[4] = { a.x, a.y, a.z, a.w };
                float bv[8] = { b0.x, b0.y, b0.z, b0.w, b1.x, b1.y, b1.z, b1.w };
                #pragma unroll
                for (int r = 0; r < 4; r++)
                    #pragma unroll
                    for (int c = 0; c < 8; c++) acc[r][c] += av[r] * bv[c];
            }
        }
        __syncthreads();
    }
    if (act) {
        #pragma unroll
        for (int r = 0; r < 4; r++)
            #pragma unroll
            for (int c = 0; c < 8; c++)
                atomicAdd(&sG[4 * ti4 + r][8 * tj8 + c], acc[r][c]);
    }
    __syncthreads();
}

// ---------------- K2: Gram-matrix k-means + proto build ----------------------
__global__ __launch_bounds__(256, 3) void kKmeansG(const float* __restrict__ query) {
    int bc = blockIdx.x;
    if (!g_cand[bc]) return;
    int b = bc / NC, c = bc % NC;
    int tid = threadIdx.x, lane = tid & 31, warp = tid >> 5;

    if (tid == 0) {
        int pos = atomicAdd(&g_nvalid, 1);
        g_vpos[bc] = pos;
        g_vlist[pos] = bc;
    }

    __shared__ int   s_list[NM];
    __shared__ float sG[CAP][CAP+1];
    __shared__ float sXk[CH][XSTR];
    __shared__ float sw[NJ][CAP];
    __shared__ int   ncnt[NJ];
    __shared__ float sscore[NJ];
    __shared__ int   s_cnt;
    __shared__ int   s_ord[NJ];
    __shared__ float red[8][9];

    if (warp == 0) {
        int cnt = 0;
        for (int base = 0; base < NM; base += 32) {
            int m = base + lane;
            int a = (m < NM) ? g_assign[b * NM + m] : -1;
            unsigned msk = __ballot_sync(0xffffffffu, a == c);
            if (a == c) s_list[cnt + __popc(msk & ((1u << lane) - 1u))] = m;
            cnt += __popc(msk);
        }
        if (lane == 0) s_cnt = cnt;
    }
    __syncthreads();
    int count = s_cnt;
    if (count > CAP) return;

    for (int i = tid; i < CAP * (CAP + 1); i += 256) (&sG[0][0])[i] = 0.f;
    for (int i = tid; i < NJ * CAP; i += 256) {
        int j = i >> 6, p = i & 63;
        sw[j][p] = (p == j) ? 1.f : 0.f;
    }

    const float* qb = query + (size_t)b * NN * ND;

    {
        int nt4 = (count + 3) >> 2, nt8 = (count + 7) >> 3;
        int tiles = nt4 * nt8;
        if      (tiles <= 8)   gramCompute<32>(qb, s_list, count, nt4, nt8, sXk, sG, tid);
        else if (tiles <= 16)  gramCompute<16>(qb, s_list, count, nt4, nt8, sXk, sG, tid);
        else if (tiles <= 32)  gramCompute<8> (qb, s_list, count, nt4, nt8, sXk, sG, tid);
        else if (tiles <= 64)  gramCompute<4> (qb, s_list, count, nt4, nt8, sXk, sG, tid);
        else if (tiles <= 128) gramCompute<2> (qb, s_list, count, nt4, nt8, sXk, sG, tid);
        else                   gramCompute<1> (qb, s_list, count, nt4, nt8, sXk, sG, tid);
    }

    int p = tid;
    bool pact = (p < count);
    float smvp = pact ? g_sm[b * NM + s_list[p]] : 0.f;
    float c2fin[NJ] = {0.f, 0.f, 0.f};

    for (int t = 0; t <= 10; t++) {
        if (tid < NJ) { ncnt[tid] = 0; sscore[tid] = 0.f; }
        float S0 = 0.f, S1 = 0.f, S2 = 0.f;
        if (pact) {
            for (int p2 = 0; p2 < count; p2++) {
                float g = sG[p][p2];
                S0 += sw[0][p2] * g;
                S1 += sw[1][p2] * g;
                S2 += sw[2][p2] * g;
            }
        }
        float v3[NJ];
        v3[0] = pact ? sw[0][p] * S0 : 0.f;
        v3[1] = pact ? sw[1][p] * S1 : 0.f;
        v3[2] = pact ? sw[2][p] * S2 : 0.f;
        bsumN<NJ>(v3, red);
        int jb = 0;
        if (pact) {
            float e0 = v3[0] - 2.f * S0;
            float e1 = v3[1] - 2.f * S1;
            float e2 = v3[2] - 2.f * S2;
            float be = e0;
            if (e1 < be) { be = e1; jb = 1; }
            if (e2 < be) { be = e2; jb = 2; }
            atomicAdd(&ncnt[jb], 1);
            if (t == 10) atomicAdd(&sscore[jb], smvp);
        }
        __syncthreads();
        if (t < 10) {
            if (pact) {
                int n0 = ncnt[0], n1 = ncnt[1], n2 = ncnt[2];
                if (n0 > 0) sw[0][p] = (jb == 0) ? 1.f / (float)n0 : 0.f;
                if (n1 > 0) sw[1][p] = (jb == 1) ? 1.f / (float)n1 : 0.f;
                if (n2 > 0) sw[2][p] = (jb == 2) ? 1.f / (float)n2 : 0.f;
            }
            __syncthreads();
        } else {
            c2fin[0] = v3[0]; c2fin[1] = v3[1]; c2fin[2] = v3[2];
        }
    }

    if (tid == 0) {
        float avg[NJ];
        for (int j = 0; j < NJ; j++)
            avg[j] = (ncnt[j] > 0) ? sscore[j] / (float)ncnt[j] : -INFINITY;
        bool used[NJ] = {false, false, false};
        for (int s = 0; s < NJ; s++) {
            int bi = -1; float bv = 0.f;
            for (int j = 0; j < NJ; j++) {
                if (used[j]) continue;
                if (bi < 0 || avg[j] > bv) { bi = j; bv = avg[j]; }
            }
            used[bi] = true; s_ord[s] = bi;
        }
    }

    int myd = tid * 4;
    float4 a0 = make_float4(0.f,0.f,0.f,0.f), a1 = a0, a2 = a0, cs = a0;
    __syncthreads();
    for (int pp = 0; pp < count; pp++) {
        float w0 = sw[0][pp], w1 = sw[1][pp], w2 = sw[2][pp];
        float4 v = *(const float4*)(qb + (size_t)(2 * s_list[pp]) * ND + myd);
        cs.x += v.x; cs.y += v.y; cs.z += v.z; cs.w += v.w;
        a0.x += w0*v.x; a0.y += w0*v.y; a0.z += w0*v.z; a0.w += w0*v.w;
        a1.x += w1*v.x; a1.y += w1*v.y; a1.z += w1*v.z; a1.w += w1*v.w;
        a2.x += w2*v.x; a2.y += w2*v.y; a2.z += w2*v.z; a2.w += w2*v.w;
    }
    float invden = 1.0f / (float)((NM - count) > 1 ? (NM - count) : 1);
    float4 tsv = *(const float4*)(g_totsum + b * ND + myd);
    float4 bb = make_float4((tsv.x - cs.x)*invden, (tsv.y - cs.y)*invden,
                            (tsv.z - cs.z)*invden, (tsv.w - cs.w)*invden);
    float nb[1] = { bb.x*bb.x + bb.y*bb.y + bb.z*bb.z + bb.w*bb.w };
    bsumN<1>(nb, red);

    float* out = g_ph + (size_t)bc * 4 * ND;
    #pragma unroll
    for (int jj = 0; jj < NJ; jj++) {
        int sj = s_ord[jj];
        float4 av = (sj == 0) ? a0 : ((sj == 1) ? a1 : a2);
        float scale = 1.0f / fmaxf(sqrtf(c2fin[sj]), 1e-12f);
        *(float4*)(out + (size_t)jj * ND + myd) =
            make_float4(av.x*scale, av.y*scale, av.z*scale, av.w*scale);
    }
    {
        float scale = 1.0f / fmaxf(sqrtf(nb[0]), 1e-12f);
        *(float4*)(out + (size_t)3 * ND + myd) =
            make_float4(bb.x*scale, bb.y*scale, bb.z*scale, bb.w*scale);
    }
}

// ---------------- K2b: fallback for count > CAP (rare; usually exits) --------
__global__ __launch_bounds__(256) void kKmeansBig(const float* __restrict__ query) {
    int bc = blockIdx.x;
    if (!g_big[bc]) return;
    int b = bc / NC, c = bc % NC;
    int tid = threadIdx.x, lane = tid & 31, warp = tid >> 5;

    __shared__ float cen[NJ][ND];
    __shared__ int   s_list[NM];
    __shared__ int   s_asg[NM];
    __shared__ int   s_cnt;
    __shared__ int   skcnt[NJ];
    __shared__ float skscore[NJ];
    __shared__ float red[8][9];
    __shared__ int   s_ord[NJ];

    if (warp == 0) {
        int cnt = 0;
        for (int base = 0; base < NM; base += 32) {
            int m = base + lane;
            int a = (m < NM) ? g_assign[b * NM + m] : -1;
            unsigned msk = __ballot_sync(0xffffffffu, a == c);
            if (a == c) s_list[cnt + __popc(msk & ((1u << lane) - 1u))] = m;
            cnt += __popc(msk);
        }
        if (lane == 0) s_cnt = cnt;
    }
    __syncthreads();
    int count = s_cnt;

    const float* qb = query + (size_t)b * NN * ND;
    for (int j = 0; j < NJ; j++) {
        const float* row = qb + (size_t)(2 * s_list[j]) * ND;
        for (int d = tid; d < ND; d += 256) cen[j][d] = row[d];
    }
    float c2r[NJ];
    {
        float nv[NJ] = {0.f, 0.f, 0.f};
        __syncthreads();
        for (int d = tid; d < ND; d += 256) {
            float v0 = cen[0][d], v1 = cen[1][d], v2 = cen[2][d];
            nv[0] += v0*v0; nv[1] += v1*v1; nv[2] += v2*v2;
        }
        bsumN<NJ>(nv, red);
        c2r[0] = nv[0]; c2r[1] = nv[1]; c2r[2] = nv[2];
    }

    int myd = tid * 4;
    float4 csum = make_float4(0.f,0.f,0.f,0.f);

    for (int iter = 0; iter <= 10; iter++) {
        bool finalp = (iter == 10);
        if (tid < NJ) { skcnt[tid] = 0; skscore[tid] = 0.f; }
        __syncthreads();
        for (int p = warp; p < count; p += 8) {
            const float* row = qb + (size_t)(2 * s_list[p]) * ND;
            float d0 = 0.f, d1 = 0.f, d2 = 0.f;
            #pragma unroll
            for (int k = 0; k < 32; k++) {
                float v = row[lane + 32 * k];
                d0 += v * cen[0][lane + 32 * k];
                d1 += v * cen[1][lane + 32 * k];
                d2 += v * cen[2][lane + 32 * k];
            }
            #pragma unroll
            for (int o = 16; o > 0; o >>= 1) {
                d0 += __shfl_down_sync(0xffffffffu, d0, o);
                d1 += __shfl_down_sync(0xffffffffu, d1, o);
                d2 += __shfl_down_sync(0xffffffffu, d2, o);
            }
            if (lane == 0) {
                float e0 = c2r[0] - 2.f * d0;
                float e1 = c2r[1] - 2.f * d1;
                float e2 = c2r[2] - 2.f * d2;
                int jb = 0; float be = e0;
                if (e1 < be) { be = e1; jb = 1; }
                if (e2 < be) { be = e2; jb = 2; }
                s_asg[p] = jb;
                atomicAdd(&skcnt[jb], 1);
                if (finalp) atomicAdd(&skscore[jb], g_sm[b * NM + s_list[p]]);
            }
        }
        __syncthreads();
        if (finalp) break;

        float4 a0 = make_float4(0.f,0.f,0.f,0.f), a1 = a0, a2 = a0;
        for (int p = 0; p < count; p++) {
            int j = s_asg[p];
            float4 v = *(const float4*)(qb + (size_t)(2 * s_list[p]) * ND + myd);
            if (j == 0)      { a0.x += v.x; a0.y += v.y; a0.z += v.z; a0.w += v.w; }
            else if (j == 1) { a1.x += v.x; a1.y += v.y; a1.z += v.z; a1.w += v.w; }
            else             { a2.x += v.x; a2.y += v.y; a2.z += v.z; a2.w += v.w; }
        }
        if (iter == 9) {
            csum.x = a0.x + a1.x + a2.x; csum.y = a0.y + a1.y + a2.y;
            csum.z = a0.z + a1.z + a2.z; csum.w = a0.w + a1.w + a2.w;
        }
        float nv[NJ];
        float4* accs[NJ] = { &a0, &a1, &a2 };
        #pragma unroll
        for (int j = 0; j < NJ; j++) {
            int cnt = skcnt[j];
            float4 cur = make_float4(cen[j][myd], cen[j][myd+1], cen[j][myd+2], cen[j][myd+3]);
            float4 nw;
            if (cnt > 0) {
                float inv = 1.0f / (float)cnt;
                nw = make_float4(accs[j]->x*inv, accs[j]->y*inv, accs[j]->z*inv, accs[j]->w*inv);
            } else nw = cur;
            cen[j][myd]   = nw.x; cen[j][myd+1] = nw.y;
            cen[j][myd+2] = nw.z; cen[j][myd+3] = nw.w;
            nv[j] = nw.x*nw.x + nw.y*nw.y + nw.z*nw.z + nw.w*nw.w;
        }
        bsumN<NJ>(nv, red);
        c2r[0] = nv[0]; c2r[1] = nv[1]; c2r[2] = nv[2];
    }

    if (tid == 0) {
        float avg[NJ];
        for (int j = 0; j < NJ; j++)
            avg[j] = (skcnt[j] > 0) ? skscore[j] / (float)skcnt[j] : -INFINITY;
        bool used[NJ] = {false, false, false};
        for (int s = 0; s < NJ; s++) {
            int bi = -1; float bv = 0.f;
            for (int j = 0; j < NJ; j++) {
                if (used[j]) continue;
                if (bi < 0 || avg[j] > bv) { bi = j; bv = avg[j]; }
            }
            used[bi] = true; s_ord[s] = bi;
        }
    }

    float invden = 1.0f / (float)((NM - count) > 1 ? (NM - count) : 1);
    float4 tsv = *(const float4*)(g_totsum + b * ND + myd);
    float4 bb = make_float4((tsv.x - csum.x)*invden, (tsv.y - csum.y)*invden,
                            (tsv.z - csum.z)*invden, (tsv.w - csum.w)*invden);
    float nb[1] = { bb.x*bb.x + bb.y*bb.y + bb.z*bb.z + bb.w*bb.w };
    bsumN<1>(nb, red);

    float* out = g_ph + (size_t)bc * 4 * ND;
    #pragma unroll
    for (int jj = 0; jj < NJ; jj++) {
        int sj = s_ord[jj];
        float scale = 1.0f / fmaxf(sqrtf(c2r[sj]), 1e-12f);
        *(float4*)(out + (size_t)jj * ND + myd) =
            make_float4(cen[sj][myd]*scale, cen[sj][myd+1]*scale,
                        cen[sj][myd+2]*scale, cen[sj][myd+3]*scale);
    }
    {
        float scale = 1.0f / fmaxf(sqrtf(nb[0]), 1e-12f);
        *(float4*)(out + (size_t)3 * ND + myd) =
            make_float4(bb.x*scale, bb.y*scale, bb.z*scale, bb.w*scale);
    }
}

// ---------------- K3: fp32 GEMM 128x128, 8x8 thread tile, split-K=4 ----------
#define BM 128
#define BN 128
#define BK 16
#define BMP (BM + 4)
#define BNP (BN + 4)
__global__ __launch_bounds__(256, 2) void kGemm() {
    int ncols = 4 * g_nvalid;
    int n0 = blockIdx.x * BN;
    if (n0 >= ncols) return;
    int m0 = blockIdx.y * BM;
    int kz = blockIdx.z;
    int kbase = kz * KSEG;

    __shared__ float As[2][BK][BMP];
    __shared__ float Bs[2][BK][BNP];

    int tid = threadIdx.x;
    int tx = tid & 15, ty = tid >> 4;     // 16x16; thread tile 8(m) x 8(n)
    int lrow = tid >> 2;                   // 0..63
    int lcol = (tid & 3) * 4;              // k offset

    const float* aptr[2]; bool amask[2];
    const float* bptr[2];
    #pragma unroll
    for (int r = 0; r < 2; r++) {
        int m = m0 + lrow + 64 * r;
        amask[r] = (m < NN);
        aptr[r] = g_q0h + (size_t)(amask[r] ? m : 0) * ND + kbase + lcol;
        int cl = n0 + lrow + 64 * r;
        int prow = 0;
        if (cl < ncols) prow = g_vlist[cl >> 2] * 4 + (cl & 3);
        bptr[r] = g_ph + (size_t)prow * ND + kbase + lcol;
    }

    // preload tile 0
    #pragma unroll
    for (int r = 0; r < 2; r++) {
        float4 av = amask[r] ? *(const float4*)(aptr[r]) : make_float4(0,0,0,0);
        float4 bv = *(const float4*)(bptr[r]);
        As[0][lcol+0][lrow+64*r] = av.x; As[0][lcol+1][lrow+64*r] = av.y;
        As[0][lcol+2][lrow+64*r] = av.z; As[0][lcol+3][lrow+64*r] = av.w;
        Bs[0][lcol+0][lrow+64*r] = bv.x; Bs[0][lcol+1][lrow+64*r] = bv.y;
        Bs[0][lcol+2][lrow+64*r] = bv.z; Bs[0][lcol+3][lrow+64*r] = bv.w;
    }
    __syncthreads();

    unsigned long long acc[4][8];
    #pragma unroll
    for (int i = 0; i < 4; i++)
        #pragma unroll
        for (int j = 0; j < 8; j++) acc[i][j] = 0ull;

    const int T = KSEG / BK;   // 16
    float4 pav[2], pbv[2];
    for (int t = 0; t < T; t++) {
        int cur = t & 1;
        if (t < T - 1) {
            int ko = (t + 1) * BK;
            #pragma unroll
            for (int r = 0; r < 2; r++) {
                pav[r] = amask[r] ? *(const float4*)(aptr[r] + ko) : make_float4(0,0,0,0);
                pbv[r] = *(const float4*)(bptr[r] + ko);
            }
        }
        #pragma unroll
        for (int kk = 0; kk < BK; kk++) {
            ulonglong2 palo = *(const ulonglong2*)&As[cur][kk][ty * 8];
            ulonglong2 pahi = *(const ulonglong2*)&As[cur][kk][ty * 8 + 4];
            float4 b0 = *(const float4*)&Bs[cur][kk][tx * 8];
            float4 b1 = *(const float4*)&Bs[cur][kk][tx * 8 + 4];
            unsigned long long pa[4] = { palo.x, palo.y, pahi.x, pahi.y };
            float bvv[8] = { b0.x, b0.y, b0.z, b0.w, b1.x, b1.y, b1.z, b1.w };
            #pragma unroll
            for (int j = 0; j < 8; j++) {
                unsigned long long bb = pack2(bvv[j], bvv[j]);
                #pragma unroll
                for (int i = 0; i < 4; i++) ffma2(acc[i][j], pa[i], bb);
            }
        }
        if (t < T - 1) {
            __syncthreads();
            int nxt = 1 - cur;
            #pragma unroll
            for (int r = 0; r < 2; r++) {
                As[nxt][lcol+0][lrow+64*r] = pav[r].x; As[nxt][lcol+1][lrow+64*r] = pav[r].y;
                As[nxt][lcol+2][lrow+64*r] = pav[r].z; As[nxt][lcol+3][lrow+64*r] = pav[r].w;
                Bs[nxt][lcol+0][lrow+64*r] = pbv[r].x; Bs[nxt][lcol+1][lrow+64*r] = pbv[r].y;
                Bs[nxt][lcol+2][lrow+64*r] = pbv[r].z; Bs[nxt][lcol+3][lrow+64*r] = pbv[r].w;
            }
            __syncthreads();
        }
    }

    float* pbase = g_part + (size_t)kz * NN * NCOLS;
    int colb = n0 + tx * 8;
    #pragma unroll
    for (int i = 0; i < 4; i++) {
        float r0[8], r1[8];
        #pragma unroll
        for (int j = 0; j < 8; j++) unpack2(acc[i][j], r0[j], r1[j]);
        #pragma unroll
        for (int h = 0; h < 2; h++) {
            int m = m0 + ty * 8 + 2 * i + h;
            if (m >= NN) continue;
            float* src = h ? r1 : r0;
            float* dst = pbase + (size_t)m * NCOLS + colb;
            if (colb < ncols)
                *(float4*)dst = make_float4(src[0], src[1], src[2], src[3]);
            if (colb + 4 < ncols)
                *(float4*)(dst + 4) = make_float4(src[4], src[5], src[6], src[7]);
        }
    }
}

// ---------------- K4: Sinkhorn + BCE (fused split-K reduce + exp) ------------
__global__ __launch_bounds__(256) void kSink(const float* __restrict__ weights,
                                             const int* __restrict__ gt) {
    int bc = blockIdx.x;
    if (!g_cand[bc]) return;
    int b = bc / NC, c = bc % NC;
    int tid = threadIdx.x;

    __shared__ float red[8][9];
    __shared__ float scc[4];
    __shared__ int   s_done;
    __shared__ int   s_nan;

    int pk4 = g_vpos[bc] * 4;
    const size_t ss = (size_t)NN * NCOLS;
    float4 km[4]; float rloc[4]; int rows[4]; int nown = 0;
    #pragma unroll
    for (int k = 0; k < 4; k++) {
        int n = tid + 256 * k;
        if (n < NN) {
            const float* pp = g_part + (size_t)n * NCOLS + pk4;
            float4 a = *(const float4*)(pp);
            float4 bq = *(const float4*)(pp + ss);
            float4 cq = *(const float4*)(pp + 2 * ss);
            float4 dq = *(const float4*)(pp + 3 * ss);
            float4 o;
            o.x = __expf((a.x + bq.x + cq.x + dq.x - 1.f) * 10.f);
            o.y = __expf((a.y + bq.y + cq.y + dq.y - 1.f) * 10.f);
            o.z = __expf((a.z + bq.z + cq.z + dq.z - 1.f) * 10.f);
            o.w = __expf((a.w + bq.w + cq.w + dq.w - 1.f) * 10.f);
            rows[nown] = n;
            km[nown] = o;
            rloc[nown] = 1.f;
            nown++;
        }
    }
    if (tid == 0) { scc[0] = scc[1] = scc[2] = scc[3] = 1.f; s_nan = 0; }
    __syncthreads();

    const float u  = 1.0f / (float)NN;
    const float vv = 1.0f / (float)NK;
    for (int it = 0; it < 100; it++) {
        float lc0 = scc[0], lc1 = scc[1], lc2 = scc[2], lc3 = scc[3];
        float s5[5] = {0.f, 0.f, 0.f, 0.f, 0.f};
        for (int i = 0; i < nown; i++) {
            float4 k4 = km[i];
            float den = k4.x * lc0 + k4.y * lc1 + k4.z * lc2 + k4.w * lc3;
            float r1 = u / den;
            s5[4] += fabsf(r1 - rloc[i]);
            rloc[i] = r1;
            s5[0] += k4.x * r1; s5[1] += k4.y * r1;
            s5[2] += k4.z * r1; s5[3] += k4.w * r1;
        }
        bsumN<5>(s5, red);
        if (tid == 0) {
            scc[0] = vv / s5[0]; scc[1] = vv / s5[1];
            scc[2] = vv / s5[2]; scc[3] = vv / s5[3];
            s_done = (s5[4] / (float)NN < 0.01f) ? 1 : 0;
        }
        __syncthreads();
        if (s_done) break;
    }

    float w0 = weights[0], w1 = weights[1], w2 = weights[2], w3 = weights[3];
    float lc0 = scc[0], lc1 = scc[1], lc2 = scc[2], lc3 = scc[3];
    const int* gtb = gt + b * NN;
    int nanloc = 0;
    float bces[1] = {0.f};
    for (int i = 0; i < nown; i++) {
        int n = rows[i]; float r = rloc[i];
        float t0 = r * lc0 * km[i].x;
        float t1 = r * lc1 * km[i].y;
        float t2 = r * lc2 * km[i].z;
        float t3 = r * lc3 * km[i].w;
        if (isnan(t0) || isnan(t1) || isnan(t2) || isnan(t3)) nanloc = 1;
        float pred = t0 * w0 + t1 * w1 + t2 * w2 + t3 * w3;
        float p  = fminf(fmaxf(pred, 0.f), 1.f);
        float lp = fmaxf(logf(p), -100.f);
        float lq = fmaxf(logf(1.f - p), -100.f);
        int y = (gtb[n] == c + 1);
        bces[0] += -(y ? lp : lq);
    }
    if (nanloc) atomicOr(&s_nan, 1);
    bsumN<1>(bces, red);
    if (tid == 0) {
        if (s_nan) { g_bce[bc] = 0.f; g_valid[bc] = 0; }
        else       { g_bce[bc] = bces[0] / (float)NN; g_valid[bc] = 1; }
    }
}

// ---------------- K5: final reduction ----------------------------------------
__global__ void kFinal(float* __restrict__ out) {
    __shared__ float red[8][9];
    int tid = threadIdx.x;
    float s[2] = {0.f, 0.f};
    for (int i = tid; i < NB * NC; i += 256) {
        s[0] += g_bce[i];
        s[1] += (float)g_valid[i];
    }
    bsumN<2>(s, red);
    if (tid == 0) out[0] = s[0] / (s[1] + 1e-4f);
}

// ---------------- launch -----------------------------------------------------
extern "C" void kernel_launch(void* const* d_in, const int* in_sizes, int n_in,
                              void* d_out, int out_size) {
    const float* query   = (const float*)d_in[0];
    const float* score   = (const float*)d_in[1];
    const int*   label   = (const int*)d_in[2];
    const int*   gt      = (const int*)d_in[3];
    const float* weights = (const float*)d_in[4];
    float* out = (float*)d_out;

    kPrep<<<NB + 4 * NB + NN, 256>>>(query, score, label);
    kKmeansG<<<NB * NC, 256>>>(query);
    kKmeansBig<<<NB * NC, 256>>>(query);
    kGemm<<<dim3(NCOLS / BN, (NN + BM - 1) / BM, SPLITK), 256>>>();
    kSink<<<NB * NC, 256>>>(weights, gt);
    kFinal<<<1, 256>>>(out);
}

// round 16
// speedup vs baseline: 1.5014x; 1.0061x over previous
#include <cuda_runtime.h>
#include <math.h>

#define NB 32
#define NC 20
#define NN 784
#define NM 392
#define ND 1024
#define NK 4
#define NJ 3
#define NCOLS (NB*NC*4)   // 2560 max packed columns
#define CAP 64            // max class points handled by Gram path
#define CH 64             // Gram chunk columns
#define NCH (ND/CH)       // 16 chunks
#define XSTR (CAP+4)      // sXk row stride
#define SPLITK 4
#define KSEG (ND/SPLITK)  // 256

// ---------------- scratch (device globals) ----------------------------------
__device__ int   g_assign[NB*NM];
__device__ float g_sm[NB*NM];
__device__ float g_totsum[NB*ND];
__device__ float g_q0h[NN*ND];
__device__ float g_ph[(size_t)NB*NC*4*ND];
__device__ int   g_cand[NB*NC];
__device__ int   g_big[NB*NC];
__device__ int   g_vlist[NB*NC];
__device__ int   g_vpos[NB*NC];
__device__ int   g_nvalid;
__device__ float g_part[(size_t)SPLITK*NN*NCOLS];  // 32 MB split-K partials
__device__ float g_bce[NB*NC];
__device__ int   g_valid[NB*NC];

// ---------------- helpers ----------------------------------------------------
__device__ __forceinline__ unsigned long long pack2(float x, float y) {
    unsigned long long r;
    asm("mov.b64 %0, {%1,%2};" : "=l"(r) : "f"(x), "f"(y));
    return r;
}
__device__ __forceinline__ void unpack2(unsigned long long p, float& x, float& y) {
    asm("mov.b64 {%0,%1}, %2;" : "=f"(x), "=f"(y) : "l"(p));
}
__device__ __forceinline__ void ffma2(unsigned long long& c, unsigned long long a,
                                      unsigned long long b) {
    asm("fma.rn.f32x2 %0, %1, %2, %0;" : "+l"(c) : "l"(a), "l"(b));
}

template <int N>
__device__ __forceinline__ void bsumN(float* v, float (*red)[9]) {
    int tid = threadIdx.x, lane = tid & 31, warp = tid >> 5;
    __syncthreads();
    #pragma unroll
    for (int k = 0; k < N; k++) {
        float x = v[k];
        #pragma unroll
        for (int o = 16; o > 0; o >>= 1) x += __shfl_down_sync(0xffffffffu, x, o);
        if (lane == 0) red[k][warp] = x;
    }
    __syncthreads();
    if (tid < N) {
        float s = 0.f;
        #pragma unroll
        for (int w = 0; w < 8; w++) s += red[tid][w];
        red[tid][8] = s;
    }
    __syncthreads();
    #pragma unroll
    for (int k = 0; k < N; k++) v[k] = red[k][8];
}

// ---------------- K1: fused prep (assign+candidacy | totsum | q0h) -----------
__global__ __launch_bounds__(256) void kPrep(const float* __restrict__ query,
                                             const float* __restrict__ score,
                                             const int* __restrict__ label) {
    int blk = blockIdx.x;
    int tid = threadIdx.x;

    if (blk < NB) {
        int b = blk;
        __shared__ int hist[NC];
        if (tid < NC) hist[tid] = 0;
        if (blk == 0 && tid == 0) g_nvalid = 0;
        __syncthreads();
        for (int t = tid; t < NM; t += 256) {
            const float4* s4 = (const float4*)(score + ((size_t)b * NN + 2 * t) * NC);
            float sv[NC];
            #pragma unroll
            for (int q = 0; q < 5; q++) {
                float4 v = s4[q];
                sv[q*4+0] = v.x; sv[q*4+1] = v.y; sv[q*4+2] = v.z; sv[q*4+3] = v.w;
            }
            float best = sv[0]; int bi = 0; float sum = sv[0];
            #pragma unroll
            for (int c = 1; c < NC; c++) {
                float v = sv[c];
                sum += v;
                if (v > best) { best = v; bi = c; }
            }
            g_assign[b * NM + t] = bi;
            g_sm[b * NM + t]     = sum / (float)NC;
            atomicAdd(&hist[bi], 1);
        }
        __syncthreads();
        if (tid < NC) {
            int cnt = hist[tid];
            int cand = (label[b * NC + tid] > 0) && (cnt >= NK);
            int bc = b * NC + tid;
            g_cand[bc] = cand;
            g_big[bc]  = cand && (cnt > CAP);
            if (!cand) { g_bce[bc] = 0.f; g_valid[bc] = 0; }
        }
    } else if (blk < NB + 4 * NB) {
        int i = blk - NB;
        int b = i >> 2;
        int d = (i & 3) * 256 + tid;
        const float* q = query + (size_t)b * NN * ND + d;
        float s = 0.f;
        #pragma unroll 4
        for (int m = 0; m < NM; m++) s += q[(size_t)(2 * m) * ND];
        g_totsum[b * ND + d] = s;
    } else {
        int n = blk - NB - 4 * NB;
        const float* q = query + (size_t)n * ND;
        __shared__ float red[1][9];
        float s[1] = {0.f};
        for (int d = tid; d < ND; d += 256) { float v = q[d]; s[0] += v * v; }
        bsumN<1>(s, red);
        float scale = 1.0f / fmaxf(sqrtf(s[0]), 1e-12f);
        for (int d = tid; d < ND; d += 256)
            g_q0h[(size_t)n * ND + d] = q[d] * scale;
    }
}

// ---------------- Gram compute: pipelined staging + 4x8 register tiles -------
template <int KS>
__device__ __forceinline__ void gramCompute(
    const float* qb, const int* s_list, int count, int nt4, int nt8,
    float (*sXk)[XSTR], float (*sG)[CAP+1], int tid)
{
    int tiles = nt4 * nt8;
    int tile = tid / KS, ksid = tid % KS;
    bool act = (tile < tiles);
    int ti4 = act ? (tile % nt4) : 0;
    int tj8 = act ? (tile / nt4) : 0;

    float acc[4][8];
    #pragma unroll
    for (int r = 0; r < 4; r++)
        #pragma unroll
        for (int c = 0; c < 8; c++) acc[r][c] = 0.f;

    int nload = count * 16;
    float4 pf[4];

    #pragma unroll
    for (int e = 0; e < 4; e++) {
        int i = tid + e * 256;
        if (i < nload)
            pf[e] = *(const float4*)(qb + (size_t)(2 * s_list[i >> 4]) * ND + (i & 15) * 4);
    }

    for (int ch = 0; ch < NCH; ch++) {
        #pragma unroll
        for (int e = 0; e < 4; e++) {
            int i = tid + e * 256;
            if (i < nload) {
                int p = i >> 4, q = i & 15;
                sXk[q*4+0][p] = pf[e].x; sXk[q*4+1][p] = pf[e].y;
                sXk[q*4+2][p] = pf[e].z; sXk[q*4+3][p] = pf[e].w;
            }
        }
        __syncthreads();
        if (ch + 1 < NCH) {
            #pragma unroll
            for (int e = 0; e < 4; e++) {
                int i = tid + e * 256;
                if (i < nload)
                    pf[e] = *(const float4*)(qb + (size_t)(2 * s_list[i >> 4]) * ND
                                             + (ch + 1) * CH + (i & 15) * 4);
            }
        }
        if (act) {
            #pragma unroll 4
            for (int kk = 0; kk < CH / KS; kk++) {
                int k = ksid + kk * KS;
                float4 a  = *(const float4*)&sXk[k][4 * ti4];
                float4 b0 = *(const float4*)&sXk[k][8 * tj8];
                float4 b1 = *(const float4*)&sXk[k][8 * tj8 + 4];
                float av[4] = { a.x, a.y, a.z, a.w };
                float bv[8] = { b0.x, b0.y, b0.z, b0.w, b1.x, b1.y, b1.z, b1.w };
                #pragma unroll
                for (int r = 0; r < 4; r++)
                    #pragma unroll
                    for (int c = 0; c < 8; c++) acc[r][c] += av[r] * bv[c];
            }
        }
        __syncthreads();
    }
    if (act) {
        #pragma unroll
        for (int r = 0; r < 4; r++)
            #pragma unroll
            for (int c = 0; c < 8; c++)
                atomicAdd(&sG[4 * ti4 + r][8 * tj8 + c], acc[r][c]);
    }
    __syncthreads();
}

// ---------------- K2: Gram-matrix k-means + proto build ----------------------
__global__ __launch_bounds__(256, 3) void kKmeansG(const float* __restrict__ query) {
    int bc = blockIdx.x;
    if (!g_cand[bc]) return;
    int b = bc / NC, c = bc % NC;
    int tid = threadIdx.x, lane = tid & 31, warp = tid >> 5;

    if (tid == 0) {
        int pos = atomicAdd(&g_nvalid, 1);
        g_vpos[bc] = pos;
        g_vlist[pos] = bc;
    }

    __shared__ int   s_list[NM];
    __shared__ float sG[CAP][CAP+1];
    __shared__ float sXk[CH][XSTR];
    __shared__ float sw[NJ][CAP];
    __shared__ int   ncnt[NJ];
    __shared__ float sscore[NJ];
    __shared__ int   s_cnt;
    __shared__ int   s_ord[NJ];
    __shared__ float red[8][9];

    if (warp == 0) {
        int cnt = 0;
        for (int base = 0; base < NM; base += 32) {
            int m = base + lane;
            int a = (m < NM) ? g_assign[b * NM + m] : -1;
            unsigned msk = __ballot_sync(0xffffffffu, a == c);
            if (a == c) s_list[cnt + __popc(msk & ((1u << lane) - 1u))] = m;
            cnt += __popc(msk);
        }
        if (lane == 0) s_cnt = cnt;
    }
    __syncthreads();
    int count = s_cnt;
    if (count > CAP) return;

    for (int i = tid; i < CAP * (CAP + 1); i += 256) (&sG[0][0])[i] = 0.f;
    for (int i = tid; i < NJ * CAP; i += 256) {
        int j = i >> 6, p = i & 63;
        sw[j][p] = (p == j) ? 1.f : 0.f;
    }

    const float* qb = query + (size_t)b * NN * ND;

    {
        int nt4 = (count + 3) >> 2, nt8 = (count + 7) >> 3;
        int tiles = nt4 * nt8;
        if      (tiles <= 8)   gramCompute<32>(qb, s_list, count, nt4, nt8, sXk, sG, tid);
        else if (tiles <= 16)  gramCompute<16>(qb, s_list, count, nt4, nt8, sXk, sG, tid);
        else if (tiles <= 32)  gramCompute<8> (qb, s_list, count, nt4, nt8, sXk, sG, tid);
        else if (tiles <= 64)  gramCompute<4> (qb, s_list, count, nt4, nt8, sXk, sG, tid);
        else if (tiles <= 128) gramCompute<2> (qb, s_list, count, nt4, nt8, sXk, sG, tid);
        else                   gramCompute<1> (qb, s_list, count, nt4, nt8, sXk, sG, tid);
    }

    int p = tid;
    bool pact = (p < count);
    float smvp = pact ? g_sm[b * NM + s_list[p]] : 0.f;
    float c2fin[NJ] = {0.f, 0.f, 0.f};

    for (int t = 0; t <= 10; t++) {
        if (tid < NJ) { ncnt[tid] = 0; sscore[tid] = 0.f; }
        float S0 = 0.f, S1 = 0.f, S2 = 0.f;
        if (pact) {
            for (int p2 = 0; p2 < count; p2++) {
                float g = sG[p][p2];
                S0 += sw[0][p2] * g;
                S1 += sw[1][p2] * g;
                S2 += sw[2][p2] * g;
            }
        }
        float v3[NJ];
        v3[0] = pact ? sw[0][p] * S0 : 0.f;
        v3[1] = pact ? sw[1][p] * S1 : 0.f;
        v3[2] = pact ? sw[2][p] * S2 : 0.f;
        bsumN<NJ>(v3, red);
        int jb = 0;
        if (pact) {
            float e0 = v3[0] - 2.f * S0;
            float e1 = v3[1] - 2.f * S1;
            float e2 = v3[2] - 2.f * S2;
            float be = e0;
            if (e1 < be) { be = e1; jb = 1; }
            if (e2 < be) { be = e2; jb = 2; }
            atomicAdd(&ncnt[jb], 1);
            if (t == 10) atomicAdd(&sscore[jb], smvp);
        }
        __syncthreads();
        if (t < 10) {
            if (pact) {
                int n0 = ncnt[0], n1 = ncnt[1], n2 = ncnt[2];
                if (n0 > 0) sw[0][p] = (jb == 0) ? 1.f / (float)n0 : 0.f;
                if (n1 > 0) sw[1][p] = (jb == 1) ? 1.f / (float)n1 : 0.f;
                if (n2 > 0) sw[2][p] = (jb == 2) ? 1.f / (float)n2 : 0.f;
            }
            __syncthreads();
        } else {
            c2fin[0] = v3[0]; c2fin[1] = v3[1]; c2fin[2] = v3[2];
        }
    }

    if (tid == 0) {
        float avg[NJ];
        for (int j = 0; j < NJ; j++)
            avg[j] = (ncnt[j] > 0) ? sscore[j] / (float)ncnt[j] : -INFINITY;
        bool used[NJ] = {false, false, false};
        for (int s = 0; s < NJ; s++) {
            int bi = -1; float bv = 0.f;
            for (int j = 0; j < NJ; j++) {
                if (used[j]) continue;
                if (bi < 0 || avg[j] > bv) { bi = j; bv = avg[j]; }
            }
            used[bi] = true; s_ord[s] = bi;
        }
    }

    int myd = tid * 4;
    float4 a0 = make_float4(0.f,0.f,0.f,0.f), a1 = a0, a2 = a0, cs = a0;
    __syncthreads();
    for (int pp = 0; pp < count; pp++) {
        float w0 = sw[0][pp], w1 = sw[1][pp], w2 = sw[2][pp];
        float4 v = *(const float4*)(qb + (size_t)(2 * s_list[pp]) * ND + myd);
        cs.x += v.x; cs.y += v.y; cs.z += v.z; cs.w += v.w;
        a0.x += w0*v.x; a0.y += w0*v.y; a0.z += w0*v.z; a0.w += w0*v.w;
        a1.x += w1*v.x; a1.y += w1*v.y; a1.z += w1*v.z; a1.w += w1*v.w;
        a2.x += w2*v.x; a2.y += w2*v.y; a2.z += w2*v.z; a2.w += w2*v.w;
    }
    float invden = 1.0f / (float)((NM - count) > 1 ? (NM - count) : 1);
    float4 tsv = *(const float4*)(g_totsum + b * ND + myd);
    float4 bb = make_float4((tsv.x - cs.x)*invden, (tsv.y - cs.y)*invden,
                            (tsv.z - cs.z)*invden, (tsv.w - cs.w)*invden);
    float nb[1] = { bb.x*bb.x + bb.y*bb.y + bb.z*bb.z + bb.w*bb.w };
    bsumN<1>(nb, red);

    float* out = g_ph + (size_t)bc * 4 * ND;
    #pragma unroll
    for (int jj = 0; jj < NJ; jj++) {
        int sj = s_ord[jj];
        float4 av = (sj == 0) ? a0 : ((sj == 1) ? a1 : a2);
        float scale = 1.0f / fmaxf(sqrtf(c2fin[sj]), 1e-12f);
        *(float4*)(out + (size_t)jj * ND + myd) =
            make_float4(av.x*scale, av.y*scale, av.z*scale, av.w*scale);
    }
    {
        float scale = 1.0f / fmaxf(sqrtf(nb[0]), 1e-12f);
        *(float4*)(out + (size_t)3 * ND + myd) =
            make_float4(bb.x*scale, bb.y*scale, bb.z*scale, bb.w*scale);
    }
}

// ---------------- K2b: fallback for count > CAP (rare; usually exits) --------
__global__ __launch_bounds__(256) void kKmeansBig(const float* __restrict__ query) {
    int bc = blockIdx.x;
    if (!g_big[bc]) return;
    int b = bc / NC, c = bc % NC;
    int tid = threadIdx.x, lane = tid & 31, warp = tid >> 5;

    __shared__ float cen[NJ][ND];
    __shared__ int   s_list[NM];
    __shared__ int   s_asg[NM];
    __shared__ int   s_cnt;
    __shared__ int   skcnt[NJ];
    __shared__ float skscore[NJ];
    __shared__ float red[8][9];
    __shared__ int   s_ord[NJ];

    if (warp == 0) {
        int cnt = 0;
        for (int base = 0; base < NM; base += 32) {
            int m = base + lane;
            int a = (m < NM) ? g_assign[b * NM + m] : -1;
            unsigned msk = __ballot_sync(0xffffffffu, a == c);
            if (a == c) s_list[cnt + __popc(msk & ((1u << lane) - 1u))] = m;
            cnt += __popc(msk);
        }
        if (lane == 0) s_cnt = cnt;
    }
    __syncthreads();
    int count = s_cnt;

    const float* qb = query + (size_t)b * NN * ND;
    for (int j = 0; j < NJ; j++) {
        const float* row = qb + (size_t)(2 * s_list[j]) * ND;
        for (int d = tid; d < ND; d += 256) cen[j][d] = row[d];
    }
    float c2r[NJ];
    {
        float nv[NJ] = {0.f, 0.f, 0.f};
        __syncthreads();
        for (int d = tid; d < ND; d += 256) {
            float v0 = cen[0][d], v1 = cen[1][d], v2 = cen[2][d];
            nv[0] += v0*v0; nv[1] += v1*v1; nv[2] += v2*v2;
        }
        bsumN<NJ>(nv, red);
        c2r[0] = nv[0]; c2r[1] = nv[1]; c2r[2] = nv[2];
    }

    int myd = tid * 4;
    float4 csum = make_float4(0.f,0.f,0.f,0.f);

    for (int iter = 0; iter <= 10; iter++) {
        bool finalp = (iter == 10);
        if (tid < NJ) { skcnt[tid] = 0; skscore[tid] = 0.f; }
        __syncthreads();
        for (int p = warp; p < count; p += 8) {
            const float* row = qb + (size_t)(2 * s_list[p]) * ND;
            float d0 = 0.f, d1 = 0.f, d2 = 0.f;
            #pragma unroll
            for (int k = 0; k < 32; k++) {
                float v = row[lane + 32 * k];
                d0 += v * cen[0][lane + 32 * k];
                d1 += v * cen[1][lane + 32 * k];
                d2 += v * cen[2][lane + 32 * k];
            }
            #pragma unroll
            for (int o = 16; o > 0; o >>= 1) {
                d0 += __shfl_down_sync(0xffffffffu, d0, o);
                d1 += __shfl_down_sync(0xffffffffu, d1, o);
                d2 += __shfl_down_sync(0xffffffffu, d2, o);
            }
            if (lane == 0) {
                float e0 = c2r[0] - 2.f * d0;
                float e1 = c2r[1] - 2.f * d1;
                float e2 = c2r[2] - 2.f * d2;
                int jb = 0; float be = e0;
                if (e1 < be) { be = e1; jb = 1; }
                if (e2 < be) { be = e2; jb = 2; }
                s_asg[p] = jb;
                atomicAdd(&skcnt[jb], 1);
                if (finalp) atomicAdd(&skscore[jb], g_sm[b * NM + s_list[p]]);
            }
        }
        __syncthreads();
        if (finalp) break;

        float4 a0 = make_float4(0.f,0.f,0.f,0.f), a1 = a0, a2 = a0;
        for (int p = 0; p < count; p++) {
            int j = s_asg[p];
            float4 v = *(const float4*)(qb + (size_t)(2 * s_list[p]) * ND + myd);
            if (j == 0)      { a0.x += v.x; a0.y += v.y; a0.z += v.z; a0.w += v.w; }
            else if (j == 1) { a1.x += v.x; a1.y += v.y; a1.z += v.z; a1.w += v.w; }
            else             { a2.x += v.x; a2.y += v.y; a2.z += v.z; a2.w += v.w; }
        }
        if (iter == 9) {
            csum.x = a0.x + a1.x + a2.x; csum.y = a0.y + a1.y + a2.y;
            csum.z = a0.z + a1.z + a2.z; csum.w = a0.w + a1.w + a2.w;
        }
        float nv[NJ];
        float4* accs[NJ] = { &a0, &a1, &a2 };
        #pragma unroll
        for (int j = 0; j < NJ; j++) {
            int cnt = skcnt[j];
            float4 cur = make_float4(cen[j][myd], cen[j][myd+1], cen[j][myd+2], cen[j][myd+3]);
            float4 nw;
            if (cnt > 0) {
                float inv = 1.0f / (float)cnt;
                nw = make_float4(accs[j]->x*inv, accs[j]->y*inv, accs[j]->z*inv, accs[j]->w*inv);
            } else nw = cur;
            cen[j][myd]   = nw.x; cen[j][myd+1] = nw.y;
            cen[j][myd+2] = nw.z; cen[j][myd+3] = nw.w;
            nv[j] = nw.x*nw.x + nw.y*nw.y + nw.z*nw.z + nw.w*nw.w;
        }
        bsumN<NJ>(nv, red);
        c2r[0] = nv[0]; c2r[1] = nv[1]; c2r[2] = nv[2];
    }

    if (tid == 0) {
        float avg[NJ];
        for (int j = 0; j < NJ; j++)
            avg[j] = (skcnt[j] > 0) ? skscore[j] / (float)skcnt[j] : -INFINITY;
        bool used[NJ] = {false, false, false};
        for (int s = 0; s < NJ; s++) {
            int bi = -1; float bv = 0.f;
            for (int j = 0; j < NJ; j++) {
                if (used[j]) continue;
                if (bi < 0 || avg[j] > bv) { bi = j; bv = avg[j]; }
            }
            used[bi] = true; s_ord[s] = bi;
        }
    }

    float invden = 1.0f / (float)((NM - count) > 1 ? (NM - count) : 1);
    float4 tsv = *(const float4*)(g_totsum + b * ND + myd);
    float4 bb = make_float4((tsv.x - csum.x)*invden, (tsv.y - csum.y)*invden,
                            (tsv.z - csum.z)*invden, (tsv.w - csum.w)*invden);
    float nb[1] = { bb.x*bb.x + bb.y*bb.y + bb.z*bb.z + bb.w*bb.w };
    bsumN<1>(nb, red);

    float* out = g_ph + (size_t)bc * 4 * ND;
    #pragma unroll
    for (int jj = 0; jj < NJ; jj++) {
        int sj = s_ord[jj];
        float scale = 1.0f / fmaxf(sqrtf(c2r[sj]), 1e-12f);
        *(float4*)(out + (size_t)jj * ND + myd) =
            make_float4(cen[sj][myd]*scale, cen[sj][myd+1]*scale,
                        cen[sj][myd+2]*scale, cen[sj][myd+3]*scale);
    }
    {
        float scale = 1.0f / fmaxf(sqrtf(nb[0]), 1e-12f);
        *(float4*)(out + (size_t)3 * ND + myd) =
            make_float4(bb.x*scale, bb.y*scale, bb.z*scale, bb.w*scale);
    }
}

// ---------------- K3: fp32 GEMM 128x64, split-K=4, 3 CTAs/SM -----------------
#define BM 128
#define BN 64
#define BK 16
#define BMP (BM + 4)
#define BNP (BN + 4)
__global__ __launch_bounds__(256, 3) void kGemm() {
    int ncols = 4 * g_nvalid;
    int n0 = blockIdx.x * BN;
    if (n0 >= ncols) return;
    int m0 = blockIdx.y * BM;
    int kz = blockIdx.z;
    int kbase = kz * KSEG;

    __shared__ float As[2][BK][BMP];
    __shared__ float Bs[2][BK][BNP];

    int tid = threadIdx.x;
    int tx = tid & 15, ty = tid >> 4;
    int lrow = tid >> 2;
    int lcol = (tid & 3) * 4;

    const float* aptr[2]; bool amask[2];
    #pragma unroll
    for (int r = 0; r < 2; r++) {
        int m = m0 + lrow + 64 * r;
        amask[r] = (m < NN);
        aptr[r] = g_q0h + (size_t)(amask[r] ? m : 0) * ND + kbase + lcol;
    }
    const float* bptr;
    {
        int cl = n0 + lrow;
        int prow = 0;
        if (cl < ncols) prow = g_vlist[cl >> 2] * 4 + (cl & 3);
        bptr = g_ph + (size_t)prow * ND + kbase + lcol;
    }

    #pragma unroll
    for (int r = 0; r < 2; r++) {
        float4 av = amask[r] ? *(const float4*)(aptr[r]) : make_float4(0,0,0,0);
        As[0][lcol+0][lrow+64*r] = av.x; As[0][lcol+1][lrow+64*r] = av.y;
        As[0][lcol+2][lrow+64*r] = av.z; As[0][lcol+3][lrow+64*r] = av.w;
    }
    {
        float4 bv = *(const float4*)(bptr);
        Bs[0][lcol+0][lrow] = bv.x; Bs[0][lcol+1][lrow] = bv.y;
        Bs[0][lcol+2][lrow] = bv.z; Bs[0][lcol+3][lrow] = bv.w;
    }
    __syncthreads();

    unsigned long long acc[4][4];
    #pragma unroll
    for (int i = 0; i < 4; i++)
        #pragma unroll
        for (int j = 0; j < 4; j++) acc[i][j] = 0ull;

    const int T = KSEG / BK;   // 16
    float4 pav[2], pbv;
    for (int t = 0; t < T; t++) {
        int cur = t & 1;
        if (t < T - 1) {
            int ko = (t + 1) * BK;
            #pragma unroll
            for (int r = 0; r < 2; r++)
                pav[r] = amask[r] ? *(const float4*)(aptr[r] + ko) : make_float4(0,0,0,0);
            pbv = *(const float4*)(bptr + ko);
        }
        #pragma unroll
        for (int kk = 0; kk < BK; kk++) {
            // A pairs loaded directly as f32x2 (adjacent floats) — no pack MOVs
            ulonglong2 palo = *(const ulonglong2*)&As[cur][kk][ty * 8];
            ulonglong2 pahi = *(const ulonglong2*)&As[cur][kk][ty * 8 + 4];
            float4 bv  = *(const float4*)&Bs[cur][kk][tx * 4];
            unsigned long long bb0 = pack2(bv.x, bv.x);
            unsigned long long bb1 = pack2(bv.y, bv.y);
            unsigned long long bb2 = pack2(bv.z, bv.z);
            unsigned long long bb3 = pack2(bv.w, bv.w);
            ffma2(acc[0][0], palo.x, bb0); ffma2(acc[1][0], palo.y, bb0);
            ffma2(acc[2][0], pahi.x, bb0); ffma2(acc[3][0], pahi.y, bb0);
            ffma2(acc[0][1], palo.x, bb1); ffma2(acc[1][1], palo.y, bb1);
            ffma2(acc[2][1], pahi.x, bb1); ffma2(acc[3][1], pahi.y, bb1);
            ffma2(acc[0][2], palo.x, bb2); ffma2(acc[1][2], palo.y, bb2);
            ffma2(acc[2][2], pahi.x, bb2); ffma2(acc[3][2], pahi.y, bb2);
            ffma2(acc[0][3], palo.x, bb3); ffma2(acc[1][3], palo.y, bb3);
            ffma2(acc[2][3], pahi.x, bb3); ffma2(acc[3][3], pahi.y, bb3);
        }
        if (t < T - 1) {
            __syncthreads();
            int nxt = 1 - cur;
            #pragma unroll
            for (int r = 0; r < 2; r++) {
                As[nxt][lcol+0][lrow+64*r] = pav[r].x; As[nxt][lcol+1][lrow+64*r] = pav[r].y;
                As[nxt][lcol+2][lrow+64*r] = pav[r].z; As[nxt][lcol+3][lrow+64*r] = pav[r].w;
            }
            Bs[nxt][lcol+0][lrow] = pbv.x; Bs[nxt][lcol+1][lrow] = pbv.y;
            Bs[nxt][lcol+2][lrow] = pbv.z; Bs[nxt][lcol+3][lrow] = pbv.w;
            __syncthreads();
        }
    }

    int colb = n0 + tx * 4;
    if (colb < ncols) {
        float* pbase = g_part + (size_t)kz * NN * NCOLS;
        #pragma unroll
        for (int i = 0; i < 4; i++) {
            float r0[4], r1[4];
            #pragma unroll
            for (int j = 0; j < 4; j++) unpack2(acc[i][j], r0[j], r1[j]);
            #pragma unroll
            for (int h = 0; h < 2; h++) {
                int m = m0 + ty * 8 + 2 * i + h;
                if (m >= NN) continue;
                float* src = h ? r1 : r0;
                *(float4*)(pbase + (size_t)m * NCOLS + colb) =
                    make_float4(src[0], src[1], src[2], src[3]);
            }
        }
    }
}

// ---------------- K4: Sinkhorn + BCE (fused split-K reduce + exp) ------------
__global__ __launch_bounds__(256) void kSink(const float* __restrict__ weights,
                                             const int* __restrict__ gt) {
    int bc = blockIdx.x;
    if (!g_cand[bc]) return;
    int b = bc / NC, c = bc % NC;
    int tid = threadIdx.x;

    __shared__ float red[8][9];
    __shared__ float scc[4];
    __shared__ int   s_done;
    __shared__ int   s_nan;

    int pk4 = g_vpos[bc] * 4;
    const size_t ss = (size_t)NN * NCOLS;
    float4 km[4]; float rloc[4]; int rows[4]; int nown = 0;
    #pragma unroll
    for (int k = 0; k < 4; k++) {
        int n = tid + 256 * k;
        if (n < NN) {
            const float* pp = g_part + (size_t)n * NCOLS + pk4;
            float4 a = *(const float4*)(pp);
            float4 bq = *(const float4*)(pp + ss);
            float4 cq = *(const float4*)(pp + 2 * ss);
            float4 dq = *(const float4*)(pp + 3 * ss);
            float4 o;
            o.x = __expf((a.x + bq.x + cq.x + dq.x - 1.f) * 10.f);
            o.y = __expf((a.y + bq.y + cq.y + dq.y - 1.f) * 10.f);
            o.z = __expf((a.z + bq.z + cq.z + dq.z - 1.f) * 10.f);
            o.w = __expf((a.w + bq.w + cq.w + dq.w - 1.f) * 10.f);
            rows[nown] = n;
            km[nown] = o;
            rloc[nown] = 1.f;
            nown++;
        }
    }
    if (tid == 0) { scc[0] = scc[1] = scc[2] = scc[3] = 1.f; s_nan = 0; }
    __syncthreads();

    const float u  = 1.0f / (float)NN;
    const float vv = 1.0f / (float)NK;
    for (int it = 0; it < 100; it++) {
        float lc0 = scc[0], lc1 = scc[1], lc2 = scc[2], lc3 = scc[3];
        float s5[5] = {0.f, 0.f, 0.f, 0.f, 0.f};
        for (int i = 0; i < nown; i++) {
            float4 k4 = km[i];
            float den = k4.x * lc0 + k4.y * lc1 + k4.z * lc2 + k4.w * lc3;
            float r1 = u / den;
            s5[4] += fabsf(r1 - rloc[i]);
            rloc[i] = r1;
            s5[0] += k4.x * r1; s5[1] += k4.y * r1;
            s5[2] += k4.z * r1; s5[3] += k4.w * r1;
        }
        bsumN<5>(s5, red);
        if (tid == 0) {
            scc[0] = vv / s5[0]; scc[1] = vv / s5[1];
            scc[2] = vv / s5[2]; scc[3] = vv / s5[3];
            s_done = (s5[4] / (float)NN < 0.01f) ? 1 : 0;
        }
        __syncthreads();
        if (s_done) break;
    }

    float w0 = weights[0], w1 = weights[1], w2 = weights[2], w3 = weights[3];
    float lc0 = scc[0], lc1 = scc[1], lc2 = scc[2], lc3 = scc[3];
    const int* gtb = gt + b * NN;
    int nanloc = 0;
    float bces[1] = {0.f};
    for (int i = 0; i < nown; i++) {
        int n = rows[i]; float r = rloc[i];
        float t0 = r * lc0 * km[i].x;
        float t1 = r * lc1 * km[i].y;
        float t2 = r * lc2 * km[i].z;
        float t3 = r * lc3 * km[i].w;
        if (isnan(t0) || isnan(t1) || isnan(t2) || isnan(t3)) nanloc = 1;
        float pred = t0 * w0 + t1 * w1 + t2 * w2 + t3 * w3;
        float p  = fminf(fmaxf(pred, 0.f), 1.f);
        float lp = fmaxf(__logf(p), -100.f);
        float lq = fmaxf(__logf(1.f - p), -100.f);
        int y = (gtb[n] == c + 1);
        bces[0] += -(y ? lp : lq);
    }
    if (nanloc) atomicOr(&s_nan, 1);
    bsumN<1>(bces, red);
    if (tid == 0) {
        if (s_nan) { g_bce[bc] = 0.f; g_valid[bc] = 0; }
        else       { g_bce[bc] = bces[0] / (float)NN; g_valid[bc] = 1; }
    }
}

// ---------------- K5: final reduction ----------------------------------------
__global__ void kFinal(float* __restrict__ out) {
    __shared__ float red[8][9];
    int tid = threadIdx.x;
    float s[2] = {0.f, 0.f};
    for (int i = tid; i < NB * NC; i += 256) {
        s[0] += g_bce[i];
        s[1] += (float)g_valid[i];
    }
    bsumN<2>(s, red);
    if (tid == 0) out[0] = s[0] / (s[1] + 1e-4f);
}

// ---------------- launch -----------------------------------------------------
extern "C" void kernel_launch(void* const* d_in, const int* in_sizes, int n_in,
                              void* d_out, int out_size) {
    const float* query   = (const float*)d_in[0];
    const float* score   = (const float*)d_in[1];
    const int*   label   = (const int*)d_in[2];
    const int*   gt      = (const int*)d_in[3];
    const float* weights = (const float*)d_in[4];
    float* out = (float*)d_out;

    kPrep<<<NB + 4 * NB + NN, 256>>>(query, score, label);
    kKmeansG<<<NB * NC, 256>>>(query);
    kKmeansBig<<<NB * NC, 256>>>(query);
    kGemm<<<dim3(NCOLS / BN, (NN + BM - 1) / BM, SPLITK), 256>>>();
    kSink<<<NB * NC, 256>>>(weights, gt);
    kFinal<<<1, 256>>>(out);
}